// round 8
// baseline (speedup 1.0000x reference)
#include <cuda_runtime.h>
#include <math.h>
#include <stdint.h>

#define T_ 24
#define B_ 64
#define I_ 128
#define H_ 256
#define R_ 64
#define HR 320
#define NTHR 512
#define LN_EPS 1e-5f

// ---- smem float offsets ----
#define SM_TE   0        // 128 rows * 128 float2 = 32768 floats
#define SM_H    32768    // 2*256 ping-pong h
#define SM_TEV  33280    // 2*256 ping-pong te
#define SM_Z    33792    // 2*256 ping-pong z
#define SM_V    34304    // 256
#define SM_MOD  34560    // 256
#define SM_WH   34816    // 2*320 ping-pong Wh
#define SM_SV   35456    // 256
#define SM_U    35712    // 64
#define SM_RED  35776    // 64
#define SM_TOT  35840
#define SM_BYTES (SM_TOT*4)

// ---- global scratch ----
__device__ float  g_Wx[T_*B_*HR];
__device__ float2 g_hilo[H_*H_];
__device__ float  g_ra[H_*H_];
__device__ float  g_sU[H_*H_];
__device__ float  g_sE[H_*H_];
__device__ int    g_unif;
__device__ int    g_munif;
__device__ int    g_bmin_bits;
__device__ float  g_ra0, g_sU0, g_sE0, g_m2h0;

typedef unsigned long long u64;

__device__ __forceinline__ float sigmoidf(float x) { return 1.f / (1.f + expf(-x)); }

__device__ __forceinline__ u64 pk2(float lo, float hi) {
    u64 r; asm("mov.b64 %0, {%1, %2};" : "=l"(r) : "f"(lo), "f"(hi)); return r;
}
__device__ __forceinline__ float2 upk2(u64 v) {
    float2 r; asm("mov.b64 {%0, %1}, %2;" : "=f"(r.x), "=f"(r.y) : "l"(v)); return r;
}
__device__ __forceinline__ u64 fma2(u64 a, u64 b, u64 c) {
    u64 r; asm("fma.rn.f32x2 %0, %1, %2, %3;" : "=l"(r) : "l"(a), "l"(b), "l"(c)); return r;
}
__device__ __forceinline__ u64 mul2(u64 a, u64 b) {
    u64 r; asm("mul.rn.f32x2 %0, %1, %2;" : "=l"(r) : "l"(a), "l"(b)); return r;
}
__device__ __forceinline__ u64 pkf2(float2 v) { return pk2(v.x, v.y); }

__device__ __forceinline__ uint32_t s2u(const void* p) {
    uint32_t a;
    asm("{ .reg .u64 t; cvta.to.shared.u64 t, %1; cvt.u32.u64 %0, t; }" : "=r"(a) : "l"(p));
    return a;
}
__device__ __forceinline__ uint32_t ctarank() {
    uint32_t r; asm("mov.u32 %0, %%cluster_ctarank;" : "=r"(r)); return r;
}
__device__ __forceinline__ void st_remote(uint32_t my_addr, uint32_t peer, float v) {
    uint32_t ra;
    asm volatile("mapa.shared::cluster.u32 %0, %1, %2;" : "=r"(ra) : "r"(my_addr), "r"(peer));
    asm volatile("st.shared::cluster.f32 [%0], %1;" :: "r"(ra), "f"(v) : "memory");
}
#define CLUSTER_SYNC() do { \
    asm volatile("barrier.cluster.arrive.aligned;" ::: "memory"); \
    asm volatile("barrier.cluster.wait.aligned;" ::: "memory"); } while (0)

// -------- init flags --------
__global__ void k_init() { g_unif = 1; g_munif = 1; g_bmin_bits = 0x7f7fffff; }

// -------- per-(i,j) constants; warp-reduced atomics --------
__global__ void k_prep(const float* __restrict__ alpha,
                       const float* __restrict__ tauU,
                       const float* __restrict__ tauE,
                       const float* __restrict__ h2h_w,
                       const float* __restrict__ mod2h) {
    int idx = blockIdx.x * blockDim.x + threadIdx.x;   // 0..65535
    int lane = threadIdx.x & 31;
    float a = alpha[idx], u = tauU[idx], e = tauE[idx];
    float ra = fmaxf(a, 0.f);
    g_ra[idx] = ra;
    g_sU[idx] = sigmoidf(u);
    g_sE[idx] = sigmoidf(e);
    float wv = h2h_w[idx];
    float den = ra + 1e-8f;
    float hi = fmaxf(1.f - wv, 0.f) / den;
    float lo = -fmaxf(1.f + wv, 0.f) / den;
    g_hilo[idx] = make_float2(hi, lo);
    float bnd = fminf(hi, -lo);            // >= 0
#pragma unroll
    for (int o = 16; o > 0; o >>= 1) bnd = fminf(bnd, __shfl_xor_sync(0xffffffffu, bnd, o));
    bool eq = (a == alpha[0]) && (u == tauU[0]) && (e == tauE[0]);
    bool alleq = __all_sync(0xffffffffu, eq);
    if (lane == 0) {
        atomicMin(&g_bmin_bits, __float_as_int(bnd));  // bnd >= 0: int order == float order
        if (!alleq) atomicAnd(&g_unif, 0);
    }
    if (idx < H_ * R_) {
        bool meq = (mod2h[idx] == mod2h[0]);
        bool allm = __all_sync(__activemask(), meq);
        if (lane == 0 && !allm) atomicAnd(&g_munif, 0);
    }
    if (idx == 0) {
        g_ra0 = ra; g_sU0 = sigmoidf(u); g_sE0 = sigmoidf(e); g_m2h0 = mod2h[0];
    }
}

// -------- Wx for all timesteps: LN(x_t @ x2h_w.T + x2h_b) --------
__global__ void k_wx(const float* __restrict__ x,
                     const float* __restrict__ w,
                     const float* __restrict__ bias,
                     const float* __restrict__ lng,
                     const float* __restrict__ lnb) {
    int tb = blockIdx.x;
    int k = threadIdx.x;               // 0..319
    __shared__ float sx[I_];
    __shared__ float red[20];
    if (k < I_) sx[k] = x[tb * I_ + k];
    __syncthreads();
    float acc = bias[k];
    const float4* wr = (const float4*)(w + k * I_);
#pragma unroll
    for (int m = 0; m < I_/4; m++) {
        float4 wv = wr[m];
        acc += wv.x*sx[4*m] + wv.y*sx[4*m+1] + wv.z*sx[4*m+2] + wv.w*sx[4*m+3];
    }
    float s = acc, s2 = acc*acc;
#pragma unroll
    for (int o = 16; o > 0; o >>= 1) {
        s  += __shfl_xor_sync(0xffffffffu, s,  o);
        s2 += __shfl_xor_sync(0xffffffffu, s2, o);
    }
    int wid = k >> 5, lane = k & 31;
    if (lane == 0) { red[wid] = s; red[10 + wid] = s2; }
    __syncthreads();
    if (wid == 0) {
        float a  = (lane < 10) ? red[lane] : 0.f;
        float b2 = (lane < 10) ? red[10 + lane] : 0.f;
#pragma unroll
        for (int o = 16; o > 0; o >>= 1) {
            a  += __shfl_xor_sync(0xffffffffu, a,  o);
            b2 += __shfl_xor_sync(0xffffffffu, b2, o);
        }
        if (lane == 0) { red[0] = a; red[10] = b2; }
    }
    __syncthreads();
    float mu  = red[0] * (1.f/HR);
    float inv = rsqrtf(red[10] * (1.f/HR) - mu*mu + LN_EPS);
    g_Wx[tb*HR + k] = (acc - mu) * inv * lng[k] + lnb[k];
}

// ================= main per-batch cluster kernel =================
template<bool UNIF>
__device__ __forceinline__ void run_all(
    float* sm, uint32_t smb, int b, int rank, int tid, int w, int lane,
    const float* __restrict__ h0,  const float* __restrict__ v0,
    const float* __restrict__ dU0, const float* __restrict__ te0,
    const float* __restrict__ tE0,
    const float* __restrict__ h2h_w, const float* __restrict__ h2h_b,
    const float* __restrict__ lnh_g, const float* __restrict__ lnh_b,
    const float* __restrict__ mod2h, const float* __restrict__ tau_v,
    float* __restrict__ outp)
{
    float* o_v   = outp;
    float* o_h   = outp + 16384;
    float* o_dU  = outp + 32768;
    float* o_te  = outp + 4227072;
    float* o_tE  = outp + 4243456;
    float* o_out = outp + 8437760;

    const uint32_t peer = rank ^ 1u;
    const int i0 = rank * 128;
    const int kbase = rank*160 + w*10;
    const bool munif = (g_munif != 0);
    const float m2h0 = g_m2h0;
    const float ra0 = g_ra0, sU0 = g_sU0, sE0 = g_sE0;
    const float bmin = __int_as_float(g_bmin_bits);
    const u64 c_sE2  = pk2(sE0, sE0);
    const u64 c_osE2 = pk2(1.f - sE0, 1.f - sE0);
    const u64 c_osU2 = pk2(1.f - sU0, 1.f - sU0);
    float2* smTE2 = (float2*)sm;   // SM_TE == 0

    // ---------- prologue ----------
    float r_lng = 0.f, r_lnb = 0.f;
    if (tid < HR) { r_lng = lnh_g[tid]; r_lnb = lnh_b[tid]; }

    if (tid < H_) {
        sm[SM_SV + tid]  = sigmoidf(tau_v[tid]);
        sm[SM_H + tid]   = h0[b*H_ + tid];
        sm[SM_TEV + tid] = te0[b*H_ + tid];
        sm[SM_V + tid]   = v0[b*H_ + tid];
    }
    u64 dUr2[8][4];
    {
        const float2* h0p = (const float2*)(h0 + b*H_);
        u64 h0j2[4];
#pragma unroll
        for (int m = 0; m < 4; m++) h0j2[m] = pkf2(h0p[lane + 32*m]);
#pragma unroll
        for (int is = 0; is < 8; is++) {
            int li = w*8 + is;
            int i  = i0 + li;
            const float2* drow = (const float2*)(dU0 + (size_t)(b*H_ + i)*H_);
            const float2* trow = (const float2*)(tE0 + (size_t)(b*H_ + i)*H_);
            u64 acc2 = pk2(0.f, 0.f);
#pragma unroll
            for (int m = 0; m < 4; m++) {
                int p = lane + 32*m;
                float2 d = drow[p];
                smTE2[li*128 + p] = trow[p];
                u64 dv = pkf2(d);
                dUr2[is][m] = dv;
                if (UNIF) acc2 = fma2(dv, h0j2[m], acc2);
                else {
                    const float2* rap = (const float2*)(g_ra + (size_t)i*H_);
                    acc2 = fma2(mul2(pkf2(rap[p]), dv), h0j2[m], acc2);
                }
            }
            float2 af = upk2(acc2);
            float acc = af.x + af.y;
#pragma unroll
            for (int o = 16; o > 0; o >>= 1) acc += __shfl_xor_sync(0xffffffffu, acc, o);
            if (lane == 0) {
                float zi = UNIF ? ra0 * acc : acc;
                sm[SM_Z + i] = zi;
                st_remote(smb + 4u*(SM_Z + i), peer, zi);
            }
        }
    }
    __syncthreads();
    // Wh(0) from h0 (buffer 0)
    {
        const float4* hv4 = (const float4*)&sm[SM_H];
#pragma unroll
        for (int q = 0; q < 10; q++) {
            int k = kbase + q;
            const float4* wr = (const float4*)(h2h_w + (size_t)k*H_);
            float4 wv0 = __ldg(&wr[lane]);
            float4 wv1 = __ldg(&wr[lane + 32]);
            float4 hv0 = hv4[lane];
            float4 hv1 = hv4[lane + 32];
            u64 acc2 = fma2(pk2(wv0.x, wv0.y), pk2(hv0.x, hv0.y), pk2(0.f, 0.f));
            acc2 = fma2(pk2(wv0.z, wv0.w), pk2(hv0.z, hv0.w), acc2);
            acc2 = fma2(pk2(wv1.x, wv1.y), pk2(hv1.x, hv1.y), acc2);
            acc2 = fma2(pk2(wv1.z, wv1.w), pk2(hv1.z, hv1.w), acc2);
            float2 af = upk2(acc2);
            float acc = af.x + af.y;
#pragma unroll
            for (int o = 16; o > 0; o >>= 1) acc += __shfl_xor_sync(0xffffffffu, acc, o);
            if (lane == 0) {
                float vv = acc + __ldg(&h2h_b[k]);
                sm[SM_WH + k] = vv;
                st_remote(smb + 4u*(SM_WH + k), peer, vv);
            }
        }
    }
    CLUSTER_SYNC();

    // ---------- time loop ----------
    for (int t = 0; t < T_; t++) {
        const int hO  = SM_H   + (t & 1)*H_;
        const int hN  = SM_H   + ((t+1) & 1)*H_;
        const int teO = SM_TEV + (t & 1)*H_;
        const int teN = SM_TEV + ((t+1) & 1)*H_;
        const int zR  = SM_Z   + (t & 1)*H_;
        const int zW  = SM_Z   + ((t+1) & 1)*H_;
        const int whR = SM_WH  + (t & 1)*HR;
        const int whW = SM_WH  + ((t+1) & 1)*HR;
        const bool doWh = (t < T_ - 1);

        // ---- small phase (redundant in both CTAs; no cross-CTA exchange) ----
        float wxv = 0.f;
        if (tid < HR) wxv = __ldg(&g_Wx[(t*B_ + b)*HR + tid]);

        if (w == 0) {   // LN stats, one warp
            float s = 0.f, s2 = 0.f;
#pragma unroll
            for (int e = 0; e < 10; e++) {
                float vv = sm[whR + lane + 32*e];
                s += vv; s2 += vv*vv;
            }
#pragma unroll
            for (int o = 16; o > 0; o >>= 1) {
                s  += __shfl_xor_sync(0xffffffffu, s,  o);
                s2 += __shfl_xor_sync(0xffffffffu, s2, o);
            }
            if (lane == 0) {
                float mu = s * (1.f/HR);
                sm[SM_RED]     = mu;
                sm[SM_RED + 1] = rsqrtf(s2 * (1.f/HR) - mu*mu + LN_EPS);
            }
        }
        __syncthreads();
        float mu  = sm[SM_RED];
        float inv = sm[SM_RED + 1];
        float whv = 0.f;
        if (tid < HR) {
            whv = (sm[whR + tid] - mu) * inv * r_lng + r_lnb;
            if (tid >= H_) {
                float uval = fmaxf(wxv + whv, 0.f);
                sm[SM_U + tid - H_] = uval;
                if (munif) {   // warps 8,9: fold mod partial sums
#pragma unroll
                    for (int o = 16; o > 0; o >>= 1)
                        uval += __shfl_xor_sync(0xffffffffu, uval, o);
                    if (lane == 0) sm[SM_RED + 40 + (w - 8)] = uval;
                }
            }
        }
        __syncthreads();
        if (tid < H_) {
            float sv = sm[SM_SV + tid];
            float dv = wxv + whv + sm[zR + tid];
            float vo = sm[SM_V + tid];
            float vn = (1.f - sv) * vo + sv * dv;
            sm[SM_V + tid] = vn;
            float nh = fmaxf(vn, 0.f);
            sm[hN + tid] = nh;
            float teo = sm[teO + tid];
            sm[teN + tid] = (1.f - sv) * teo + sv * sm[hO + tid];
            if ((tid >> 7) == rank) o_out[(t*B_ + b)*H_ + tid] = nh;
            float mv;
            if (munif) {
                mv = m2h0 * (sm[SM_RED + 40] + sm[SM_RED + 41]);
            } else {
                mv = 0.f;
                const float4* mr = (const float4*)(mod2h + tid*R_);
#pragma unroll
                for (int r = 0; r < 16; r++) {
                    float4 m4 = __ldg(mr + r);
                    mv += m4.x*sm[SM_U + 4*r] + m4.y*sm[SM_U + 4*r+1]
                        + m4.z*sm[SM_U + 4*r+2] + m4.w*sm[SM_U + 4*r+3];
                }
            }
            sm[SM_MOD + tid] = mv;
        }
        __syncthreads();

        // ---- merged phase: big update (t) + Wh (t+1) overlapped ----
        {
            const float2* hOp  = (const float2*)&sm[hO];
            const float2* teOp = (const float2*)&sm[teO];
            const float2* hNp  = (const float2*)&sm[hN];
            const float4* hv4  = (const float4*)&sm[hN];
            u64 hnj2[4];
#pragma unroll
            for (int m = 0; m < 4; m++) hnj2[m] = pkf2(hNp[lane + 32*m]);

#pragma unroll
            for (int is = 0; is < 8; is++) {
                // kick off Wh row q=is loads (latency hidden by big row below)
                float4 wv0, wv1;
                if (doWh) {
                    const float4* wr = (const float4*)(h2h_w + (size_t)(kbase + is)*H_);
                    wv0 = __ldg(&wr[lane]);
                    wv1 = __ldg(&wr[lane + 32]);
                }
                int li = w*8 + is;
                int i  = i0 + li;
                float nh_i  = sm[hN + i];
                float nte_i = sm[teN + i];
                float mod_i = sm[SM_MOD + i];
                u64 nh2   = pk2(nh_i, nh_i);
                u64 mnte2 = pk2(-nte_i, -nte_i);
                u64 acc2  = pk2(0.f, 0.f);
                if (UNIF) {
                    float cm = sU0 * mod_i;
                    u64 cm2 = pk2(cm, cm);
#pragma unroll
                    for (int m = 0; m < 4; m++) {
                        int p = lane + 32*m;
                        int idx = li*128 + p;
                        u64 ho2 = pkf2(hOp[p]);
                        u64 te2 = pkf2(teOp[p]);
                        u64 tEo = pkf2(smTE2[idx]);
                        u64 a   = fma2(mnte2, ho2, mul2(nh2, te2));
                        u64 tEn = fma2(c_sE2, a, mul2(c_osE2, tEo));
                        smTE2[idx] = upk2(tEn);
                        u64 dUn = fma2(c_osU2, dUr2[is][m], mul2(cm2, tEn));
                        float2 dv = upk2(dUn);
                        bool need = fmaxf(fabsf(dv.x), fabsf(dv.y)) > bmin;
                        if (__any_sync(0xffffffffu, need)) {   // rare exact clamp
                            if (need) {
                                int j0 = (i << 8) + 2*p;
                                float2 hl0 = __ldg(&g_hilo[j0]);
                                float2 hl1 = __ldg(&g_hilo[j0 + 1]);
                                dv.x = fmaxf(fminf(dv.x, hl0.x), hl0.y);
                                dv.y = fmaxf(fminf(dv.y, hl1.x), hl1.y);
                            }
                            dUn = pk2(dv.x, dv.y);
                        }
                        dUr2[is][m] = dUn;
                        acc2 = fma2(dUn, hnj2[m], acc2);
                    }
                } else {
#pragma unroll
                    for (int m = 0; m < 4; m++) {
                        int p = lane + 32*m;
                        int idx = li*128 + p;
                        int j0 = (i << 8) + 2*p;
                        float2 tE2 = smTE2[idx];
                        float2 se2 = *(const float2*)(g_sE + j0);
                        float2 su2 = *(const float2*)(g_sU + j0);
                        float2 ra2 = *(const float2*)(g_ra + j0);
                        float2 ho = hOp[p], te = teOp[p];
                        float2 dUo = upk2(dUr2[is][m]);
                        float ax = nh_i*te.x - nte_i*ho.x;
                        float ay = nh_i*te.y - nte_i*ho.y;
                        float tEnx = (1.f - se2.x)*tE2.x + se2.x*ax;
                        float tEny = (1.f - se2.y)*tE2.y + se2.y*ay;
                        smTE2[idx] = make_float2(tEnx, tEny);
                        float dUx = (1.f - su2.x)*dUo.x + su2.x*mod_i*tEnx;
                        float dUy = (1.f - su2.y)*dUo.y + su2.y*mod_i*tEny;
                        float2 hl0 = __ldg(&g_hilo[j0]);
                        float2 hl1 = __ldg(&g_hilo[j0 + 1]);
                        dUx = fmaxf(fminf(dUx, hl0.x), hl0.y);
                        dUy = fmaxf(fminf(dUy, hl1.x), hl1.y);
                        dUr2[is][m] = pk2(dUx, dUy);
                        acc2 = fma2(pk2(ra2.x*dUx, ra2.y*dUy), hnj2[m], acc2);
                    }
                }
                float2 af = upk2(acc2);
                float acc = af.x + af.y;
#pragma unroll
                for (int o = 16; o > 0; o >>= 1) acc += __shfl_xor_sync(0xffffffffu, acc, o);
                if (lane == 0) {
                    float zi = UNIF ? ra0 * acc : acc;
                    sm[zW + i] = zi;
                    st_remote(smb + 4u*(zW + i), peer, zi);
                }
                // finish Wh row q=is
                if (doWh) {
                    float4 hv0 = hv4[lane];
                    float4 hv1 = hv4[lane + 32];
                    u64 wa = fma2(pk2(wv0.x, wv0.y), pk2(hv0.x, hv0.y), pk2(0.f, 0.f));
                    wa = fma2(pk2(wv0.z, wv0.w), pk2(hv0.z, hv0.w), wa);
                    wa = fma2(pk2(wv1.x, wv1.y), pk2(hv1.x, hv1.y), wa);
                    wa = fma2(pk2(wv1.z, wv1.w), pk2(hv1.z, hv1.w), wa);
                    float2 wf = upk2(wa);
                    float wacc = wf.x + wf.y;
#pragma unroll
                    for (int o = 16; o > 0; o >>= 1) wacc += __shfl_xor_sync(0xffffffffu, wacc, o);
                    if (lane == 0) {
                        int k = kbase + is;
                        float vv = wacc + __ldg(&h2h_b[k]);
                        sm[whW + k] = vv;
                        st_remote(smb + 4u*(whW + k), peer, vv);
                    }
                }
            }
            // Wh tail rows q=8,9
            if (doWh) {
#pragma unroll
                for (int q = 8; q < 10; q++) {
                    int k = kbase + q;
                    const float4* wr = (const float4*)(h2h_w + (size_t)k*H_);
                    float4 wv0 = __ldg(&wr[lane]);
                    float4 wv1 = __ldg(&wr[lane + 32]);
                    float4 hv0 = hv4[lane];
                    float4 hv1 = hv4[lane + 32];
                    u64 wa = fma2(pk2(wv0.x, wv0.y), pk2(hv0.x, hv0.y), pk2(0.f, 0.f));
                    wa = fma2(pk2(wv0.z, wv0.w), pk2(hv0.z, hv0.w), wa);
                    wa = fma2(pk2(wv1.x, wv1.y), pk2(hv1.x, hv1.y), wa);
                    wa = fma2(pk2(wv1.z, wv1.w), pk2(hv1.z, hv1.w), wa);
                    float2 wf = upk2(wa);
                    float wacc = wf.x + wf.y;
#pragma unroll
                    for (int o = 16; o > 0; o >>= 1) wacc += __shfl_xor_sync(0xffffffffu, wacc, o);
                    if (lane == 0) {
                        float vv = wacc + __ldg(&h2h_b[k]);
                        sm[whW + k] = vv;
                        st_remote(smb + 4u*(whW + k), peer, vv);
                    }
                }
            }
        }
        CLUSTER_SYNC();   // one sync/step: z + Wh(t+1) exchanged
    }

    // ---------- epilogue ----------
#pragma unroll
    for (int is = 0; is < 8; is++) {
        int li = w*8 + is;
        int i  = i0 + li;
        float2* drow = (float2*)(o_dU + (size_t)(b*H_ + i)*H_);
        float2* trow = (float2*)(o_tE + (size_t)(b*H_ + i)*H_);
#pragma unroll
        for (int m = 0; m < 4; m++) {
            int p = lane + 32*m;
            drow[p] = upk2(dUr2[is][m]);
            trow[p] = smTE2[li*128 + p];
        }
    }
    if (tid < 128) {
        int idx = i0 + tid;
        o_v[b*H_ + idx]  = sm[SM_V + idx];
        o_h[b*H_ + idx]  = sm[SM_H + idx];    // T even -> final in buffer 0
        o_te[b*H_ + idx] = sm[SM_TEV + idx];
    }
}

__global__ void __launch_bounds__(NTHR, 1) __cluster_dims__(2, 1, 1)
sgru_cluster(const float* __restrict__ h0,  const float* __restrict__ v0,
             const float* __restrict__ dU0, const float* __restrict__ te0,
             const float* __restrict__ tE0,
             const float* __restrict__ h2h_w, const float* __restrict__ h2h_b,
             const float* __restrict__ lnh_g, const float* __restrict__ lnh_b,
             const float* __restrict__ mod2h, const float* __restrict__ tau_v,
             float* __restrict__ outp)
{
    extern __shared__ float sm[];
    const int tid  = threadIdx.x;
    const int w    = tid >> 5;
    const int lane = tid & 31;
    const int b    = blockIdx.x >> 1;
    const int rank = (int)ctarank();
    const uint32_t smb = s2u(sm);

    if (g_unif) run_all<true >(sm, smb, b, rank, tid, w, lane, h0, v0, dU0, te0, tE0,
                               h2h_w, h2h_b, lnh_g, lnh_b, mod2h, tau_v, outp);
    else        run_all<false>(sm, smb, b, rank, tid, w, lane, h0, v0, dU0, te0, tE0,
                               h2h_w, h2h_b, lnh_g, lnh_b, mod2h, tau_v, outp);
}

extern "C" void kernel_launch(void* const* d_in, const int* in_sizes, int n_in,
                              void* d_out, int out_size) {
    const float* x      = (const float*)d_in[0];
    const float* h0     = (const float*)d_in[1];
    const float* v0     = (const float*)d_in[2];
    const float* dU0    = (const float*)d_in[3];
    const float* te0    = (const float*)d_in[4];
    const float* tE0    = (const float*)d_in[5];
    const float* x2h_w  = (const float*)d_in[6];
    const float* x2h_b  = (const float*)d_in[7];
    const float* h2h_w  = (const float*)d_in[8];
    const float* h2h_b  = (const float*)d_in[9];
    const float* lnx_g  = (const float*)d_in[10];
    const float* lnx_b  = (const float*)d_in[11];
    const float* lnh_g  = (const float*)d_in[12];
    const float* lnh_b  = (const float*)d_in[13];
    const float* alpha  = (const float*)d_in[14];
    const float* mod2h  = (const float*)d_in[15];
    const float* tau_v  = (const float*)d_in[16];
    const float* tau_U  = (const float*)d_in[17];
    const float* tau_E  = (const float*)d_in[18];

    static int smem_set = 0;
    if (!smem_set) {
        cudaFuncSetAttribute(sgru_cluster, cudaFuncAttributeMaxDynamicSharedMemorySize, SM_BYTES);
        smem_set = 1;
    }

    k_init<<<1, 1>>>();
    k_prep<<<H_*H_/256, 256>>>(alpha, tau_U, tau_E, h2h_w, mod2h);
    k_wx<<<T_*B_, HR>>>(x, x2h_w, x2h_b, lnx_g, lnx_b);
    sgru_cluster<<<2*B_, NTHR, SM_BYTES>>>(h0, v0, dU0, te0, tE0,
                                           h2h_w, h2h_b, lnh_g, lnh_b,
                                           mod2h, tau_v, (float*)d_out);
}

// round 9
// speedup vs baseline: 1.1665x; 1.1665x over previous
#include <cuda_runtime.h>
#include <math.h>
#include <stdint.h>

#define T_ 24
#define B_ 64
#define I_ 128
#define H_ 256
#define R_ 64
#define HR 320
#define NTHR 512
#define LN_EPS 1e-5f

// ---- smem float offsets ----
#define SM_TE   0        // 128 rows * 128 float2 = 32768 floats
#define SM_H    32768    // 2*256 ping-pong h
#define SM_TEV  33280    // 2*256 ping-pong te
#define SM_Z    33792    // 2*256 ping-pong z
#define SM_V    34304    // 256
#define SM_MOD  34560    // 256
#define SM_WH   34816    // 2*320 ping-pong Wh
#define SM_SV   35456    // 256
#define SM_U    35712    // 64
#define SM_RED  35776    // 64
#define SM_TOT  35840
#define SM_BYTES (SM_TOT*4)

// ---- global scratch ----
__device__ float  g_Wx[T_*B_*HR];
__device__ float2 g_hilo[H_*H_];
__device__ float  g_ra[H_*H_];
__device__ float  g_sU[H_*H_];
__device__ float  g_sE[H_*H_];
__device__ int    g_unif;
__device__ int    g_munif;
__device__ int    g_bmin_bits;
__device__ float  g_ra0, g_sU0, g_sE0, g_m2h0;

typedef unsigned long long u64;

__device__ __forceinline__ float sigmoidf(float x) { return 1.f / (1.f + expf(-x)); }

__device__ __forceinline__ u64 pk2(float lo, float hi) {
    u64 r; asm("mov.b64 %0, {%1, %2};" : "=l"(r) : "f"(lo), "f"(hi)); return r;
}
__device__ __forceinline__ float2 upk2(u64 v) {
    float2 r; asm("mov.b64 {%0, %1}, %2;" : "=f"(r.x), "=f"(r.y) : "l"(v)); return r;
}
__device__ __forceinline__ u64 fma2(u64 a, u64 b, u64 c) {
    u64 r; asm("fma.rn.f32x2 %0, %1, %2, %3;" : "=l"(r) : "l"(a), "l"(b), "l"(c)); return r;
}
__device__ __forceinline__ u64 mul2(u64 a, u64 b) {
    u64 r; asm("mul.rn.f32x2 %0, %1, %2;" : "=l"(r) : "l"(a), "l"(b)); return r;
}
__device__ __forceinline__ u64 pkf2(float2 v) { return pk2(v.x, v.y); }

__device__ __forceinline__ uint32_t s2u(const void* p) {
    uint32_t a;
    asm("{ .reg .u64 t; cvta.to.shared.u64 t, %1; cvt.u32.u64 %0, t; }" : "=r"(a) : "l"(p));
    return a;
}
__device__ __forceinline__ uint32_t ctarank() {
    uint32_t r; asm("mov.u32 %0, %%cluster_ctarank;" : "=r"(r)); return r;
}
__device__ __forceinline__ void st_remote(uint32_t my_addr, uint32_t peer, float v) {
    uint32_t ra;
    asm volatile("mapa.shared::cluster.u32 %0, %1, %2;" : "=r"(ra) : "r"(my_addr), "r"(peer));
    asm volatile("st.shared::cluster.f32 [%0], %1;" :: "r"(ra), "f"(v) : "memory");
}
#define CLUSTER_SYNC() do { \
    asm volatile("barrier.cluster.arrive.aligned;" ::: "memory"); \
    asm volatile("barrier.cluster.wait.aligned;" ::: "memory"); } while (0)

// -------- init flags --------
__global__ void k_init() { g_unif = 1; g_munif = 1; g_bmin_bits = 0x7f7fffff; }

// -------- per-(i,j) constants; warp-reduced atomics --------
__global__ void k_prep(const float* __restrict__ alpha,
                       const float* __restrict__ tauU,
                       const float* __restrict__ tauE,
                       const float* __restrict__ h2h_w,
                       const float* __restrict__ mod2h) {
    int idx = blockIdx.x * blockDim.x + threadIdx.x;   // 0..65535
    int lane = threadIdx.x & 31;
    float a = alpha[idx], u = tauU[idx], e = tauE[idx];
    float ra = fmaxf(a, 0.f);
    g_ra[idx] = ra;
    g_sU[idx] = sigmoidf(u);
    g_sE[idx] = sigmoidf(e);
    float wv = h2h_w[idx];
    float den = ra + 1e-8f;
    float hi = fmaxf(1.f - wv, 0.f) / den;
    float lo = -fmaxf(1.f + wv, 0.f) / den;
    g_hilo[idx] = make_float2(hi, lo);
    float bnd = fminf(hi, -lo);            // >= 0
#pragma unroll
    for (int o = 16; o > 0; o >>= 1) bnd = fminf(bnd, __shfl_xor_sync(0xffffffffu, bnd, o));
    bool eq = (a == alpha[0]) && (u == tauU[0]) && (e == tauE[0]);
    bool alleq = __all_sync(0xffffffffu, eq);
    if (lane == 0) {
        atomicMin(&g_bmin_bits, __float_as_int(bnd));  // bnd >= 0: int order == float order
        if (!alleq) atomicAnd(&g_unif, 0);
    }
    if (idx < H_ * R_) {
        bool meq = (mod2h[idx] == mod2h[0]);
        bool allm = __all_sync(__activemask(), meq);
        if (lane == 0 && !allm) atomicAnd(&g_munif, 0);
    }
    if (idx == 0) {
        g_ra0 = ra; g_sU0 = sigmoidf(u); g_sE0 = sigmoidf(e); g_m2h0 = mod2h[0];
    }
}

// -------- Wx: weight-stationary. Block = batch b; thread-pair owns a row half --------
__global__ void __launch_bounds__(640, 1)
k_wx(const float* __restrict__ x,
     const float* __restrict__ w,
     const float* __restrict__ bias,
     const float* __restrict__ lng,
     const float* __restrict__ lnb) {
    int b = blockIdx.x;
    int tid = threadIdx.x;               // 0..639
    __shared__ float sx[T_*I_];          // 3072
    __shared__ float swh[T_*HR];         // 7680

    // load x[:, b, :] into smem
    for (int idx = tid; idx < T_*I_; idx += 640)
        sx[idx] = x[(idx >> 7)*(B_*I_) + b*I_ + (idx & 127)];

    int k = tid >> 1;                    // row 0..319
    int half = tid & 1;                  // which 64-wide half
    // weights for this row-half: 16 float4, register-resident
    const float4* wr = (const float4*)(w + (size_t)k*I_ + half*64);
    float4 wreg[16];
#pragma unroll
    for (int m = 0; m < 16; m++) wreg[m] = __ldg(&wr[m]);
    float bk = bias[k];
    __syncthreads();

    for (int t = 0; t < T_; t++) {
        const float4* xb4 = (const float4*)&sx[t*I_ + half*64];
        float acc = 0.f;
#pragma unroll
        for (int m = 0; m < 16; m++) {
            float4 wv = wreg[m];
            float4 xv = xb4[m];
            acc += wv.x*xv.x + wv.y*xv.y + wv.z*xv.z + wv.w*xv.w;
        }
        acc += __shfl_xor_sync(0xffffffffu, acc, 1);
        if (half == 0) swh[t*HR + k] = acc + bk;
    }
    __syncthreads();

    // LN: warp per t-row (20 warps)
    int wid = tid >> 5, lane = tid & 31;
    for (int t = wid; t < T_; t += 20) {
        float vv[10]; float s = 0.f, s2 = 0.f;
#pragma unroll
        for (int e = 0; e < 10; e++) {
            vv[e] = swh[t*HR + lane + 32*e];
            s += vv[e]; s2 += vv[e]*vv[e];
        }
#pragma unroll
        for (int o = 16; o > 0; o >>= 1) {
            s  += __shfl_xor_sync(0xffffffffu, s,  o);
            s2 += __shfl_xor_sync(0xffffffffu, s2, o);
        }
        float mu  = s * (1.f/HR);
        float inv = rsqrtf(s2 * (1.f/HR) - mu*mu + LN_EPS);
#pragma unroll
        for (int e = 0; e < 10; e++) {
            int k2 = lane + 32*e;
            g_Wx[(t*B_ + b)*HR + k2] = (vv[e] - mu) * inv * __ldg(&lng[k2]) + __ldg(&lnb[k2]);
        }
    }
}

// ================= main per-batch cluster kernel =================
template<bool UNIF>
__device__ __forceinline__ void run_all(
    float* sm, uint32_t smb, int b, int rank, int tid, int w, int lane,
    const float* __restrict__ h0,  const float* __restrict__ v0,
    const float* __restrict__ dU0, const float* __restrict__ te0,
    const float* __restrict__ tE0,
    const float* __restrict__ h2h_w, const float* __restrict__ h2h_b,
    const float* __restrict__ lnh_g, const float* __restrict__ lnh_b,
    const float* __restrict__ mod2h, const float* __restrict__ tau_v,
    float* __restrict__ outp)
{
    float* o_v   = outp;
    float* o_h   = outp + 16384;
    float* o_dU  = outp + 32768;
    float* o_te  = outp + 4227072;
    float* o_tE  = outp + 4243456;
    float* o_out = outp + 8437760;

    const uint32_t peer = rank ^ 1u;
    const int i0 = rank * 128;
    const int kbase = rank*160 + w*10;
    const bool munif = (g_munif != 0);
    const float m2h0 = g_m2h0;
    const float ra0 = g_ra0, sU0 = g_sU0, sE0 = g_sE0;
    const float bmin = __int_as_float(g_bmin_bits);
    const u64 c_sE2  = pk2(sE0, sE0);
    const u64 c_osE2 = pk2(1.f - sE0, 1.f - sE0);
    const u64 c_osU2 = pk2(1.f - sU0, 1.f - sU0);
    float2* smTE2 = (float2*)sm;   // SM_TE == 0

    // ---------- prologue ----------
    float r_lng = 0.f, r_lnb = 0.f;
    if (tid < HR) { r_lng = lnh_g[tid]; r_lnb = lnh_b[tid]; }

    if (tid < H_) {
        sm[SM_SV + tid]  = sigmoidf(tau_v[tid]);
        sm[SM_H + tid]   = h0[b*H_ + tid];
        sm[SM_TEV + tid] = te0[b*H_ + tid];
        sm[SM_V + tid]   = v0[b*H_ + tid];
    }
    u64 dUr2[8][4];
    {
        const float2* h0p = (const float2*)(h0 + b*H_);
        u64 h0j2[4];
#pragma unroll
        for (int m = 0; m < 4; m++) h0j2[m] = pkf2(h0p[lane + 32*m]);
#pragma unroll
        for (int is = 0; is < 8; is++) {
            int li = w*8 + is;
            int i  = i0 + li;
            const float2* drow = (const float2*)(dU0 + (size_t)(b*H_ + i)*H_);
            const float2* trow = (const float2*)(tE0 + (size_t)(b*H_ + i)*H_);
            u64 acc2 = pk2(0.f, 0.f);
#pragma unroll
            for (int m = 0; m < 4; m++) {
                int p = lane + 32*m;
                float2 d = drow[p];
                smTE2[li*128 + p] = trow[p];
                u64 dv = pkf2(d);
                dUr2[is][m] = dv;
                if (UNIF) acc2 = fma2(dv, h0j2[m], acc2);
                else {
                    const float2* rap = (const float2*)(g_ra + (size_t)i*H_);
                    acc2 = fma2(mul2(pkf2(rap[p]), dv), h0j2[m], acc2);
                }
            }
            float2 af = upk2(acc2);
            float acc = af.x + af.y;
#pragma unroll
            for (int o = 16; o > 0; o >>= 1) acc += __shfl_xor_sync(0xffffffffu, acc, o);
            if (lane == 0) {
                float zi = UNIF ? ra0 * acc : acc;
                sm[SM_Z + i] = zi;
                st_remote(smb + 4u*(SM_Z + i), peer, zi);
            }
        }
    }
    __syncthreads();
    // Wh(0) from h0 (buffer 0)
    {
        const float4* hv4 = (const float4*)&sm[SM_H];
#pragma unroll
        for (int q = 0; q < 10; q++) {
            int k = kbase + q;
            const float4* wr = (const float4*)(h2h_w + (size_t)k*H_);
            float4 wv0 = __ldg(&wr[lane]);
            float4 wv1 = __ldg(&wr[lane + 32]);
            float4 hv0 = hv4[lane];
            float4 hv1 = hv4[lane + 32];
            u64 acc2 = fma2(pk2(wv0.x, wv0.y), pk2(hv0.x, hv0.y), pk2(0.f, 0.f));
            acc2 = fma2(pk2(wv0.z, wv0.w), pk2(hv0.z, hv0.w), acc2);
            acc2 = fma2(pk2(wv1.x, wv1.y), pk2(hv1.x, hv1.y), acc2);
            acc2 = fma2(pk2(wv1.z, wv1.w), pk2(hv1.z, hv1.w), acc2);
            float2 af = upk2(acc2);
            float acc = af.x + af.y;
#pragma unroll
            for (int o = 16; o > 0; o >>= 1) acc += __shfl_xor_sync(0xffffffffu, acc, o);
            if (lane == 0) {
                float vv = acc + __ldg(&h2h_b[k]);
                sm[SM_WH + k] = vv;
                st_remote(smb + 4u*(SM_WH + k), peer, vv);
            }
        }
    }
    CLUSTER_SYNC();

    // ---------- time loop ----------
    for (int t = 0; t < T_; t++) {
        const int hO  = SM_H   + (t & 1)*H_;
        const int hN  = SM_H   + ((t+1) & 1)*H_;
        const int teO = SM_TEV + (t & 1)*H_;
        const int teN = SM_TEV + ((t+1) & 1)*H_;
        const int zR  = SM_Z   + (t & 1)*H_;
        const int zW  = SM_Z   + ((t+1) & 1)*H_;
        const int whR = SM_WH  + (t & 1)*HR;
        const int whW = SM_WH  + ((t+1) & 1)*HR;
        const bool doWh = (t < T_ - 1);

        // ---- small phase (redundant in both CTAs; no cross-CTA exchange) ----
        float wxv = 0.f;
        if (tid < HR) wxv = __ldg(&g_Wx[(t*B_ + b)*HR + tid]);

        if (w == 0) {   // LN stats, one warp
            float s = 0.f, s2 = 0.f;
#pragma unroll
            for (int e = 0; e < 10; e++) {
                float vv = sm[whR + lane + 32*e];
                s += vv; s2 += vv*vv;
            }
#pragma unroll
            for (int o = 16; o > 0; o >>= 1) {
                s  += __shfl_xor_sync(0xffffffffu, s,  o);
                s2 += __shfl_xor_sync(0xffffffffu, s2, o);
            }
            if (lane == 0) {
                float mu = s * (1.f/HR);
                sm[SM_RED]     = mu;
                sm[SM_RED + 1] = rsqrtf(s2 * (1.f/HR) - mu*mu + LN_EPS);
            }
        }
        __syncthreads();
        float mu  = sm[SM_RED];
        float inv = sm[SM_RED + 1];
        float whv = 0.f;
        if (tid < HR) {
            whv = (sm[whR + tid] - mu) * inv * r_lng + r_lnb;
            if (tid >= H_) {
                float uval = fmaxf(wxv + whv, 0.f);
                sm[SM_U + tid - H_] = uval;
                if (munif) {   // warps 8,9: fold mod partial sums
#pragma unroll
                    for (int o = 16; o > 0; o >>= 1)
                        uval += __shfl_xor_sync(0xffffffffu, uval, o);
                    if (lane == 0) sm[SM_RED + 40 + (w - 8)] = uval;
                }
            }
        }
        __syncthreads();
        if (tid < H_) {
            float sv = sm[SM_SV + tid];
            float dv = wxv + whv + sm[zR + tid];
            float vo = sm[SM_V + tid];
            float vn = (1.f - sv) * vo + sv * dv;
            sm[SM_V + tid] = vn;
            float nh = fmaxf(vn, 0.f);
            sm[hN + tid] = nh;
            float teo = sm[teO + tid];
            sm[teN + tid] = (1.f - sv) * teo + sv * sm[hO + tid];
            if ((tid >> 7) == rank) o_out[(t*B_ + b)*H_ + tid] = nh;
            float mv;
            if (munif) {
                mv = m2h0 * (sm[SM_RED + 40] + sm[SM_RED + 41]);
            } else {
                mv = 0.f;
                const float4* mr = (const float4*)(mod2h + tid*R_);
#pragma unroll
                for (int r = 0; r < 16; r++) {
                    float4 m4 = __ldg(mr + r);
                    mv += m4.x*sm[SM_U + 4*r] + m4.y*sm[SM_U + 4*r+1]
                        + m4.z*sm[SM_U + 4*r+2] + m4.w*sm[SM_U + 4*r+3];
                }
            }
            sm[SM_MOD + tid] = mv;
        }
        __syncthreads();

        // ---- merged phase: big update (t) + Wh (t+1) overlapped ----
        {
            const float2* hOp  = (const float2*)&sm[hO];
            const float2* teOp = (const float2*)&sm[teO];
            const float2* hNp  = (const float2*)&sm[hN];
            const float4* hv4  = (const float4*)&sm[hN];
            u64 hnj2[4];
#pragma unroll
            for (int m = 0; m < 4; m++) hnj2[m] = pkf2(hNp[lane + 32*m]);

#pragma unroll
            for (int is = 0; is < 8; is++) {
                // kick off Wh row q=is loads (latency hidden by big row below)
                float4 wv0, wv1;
                if (doWh) {
                    const float4* wr = (const float4*)(h2h_w + (size_t)(kbase + is)*H_);
                    wv0 = __ldg(&wr[lane]);
                    wv1 = __ldg(&wr[lane + 32]);
                }
                int li = w*8 + is;
                int i  = i0 + li;
                float nh_i  = sm[hN + i];
                float nte_i = sm[teN + i];
                float mod_i = sm[SM_MOD + i];
                u64 nh2   = pk2(nh_i, nh_i);
                u64 mnte2 = pk2(-nte_i, -nte_i);
                u64 acc2  = pk2(0.f, 0.f);
                if (UNIF) {
                    float cm = sU0 * mod_i;
                    u64 cm2 = pk2(cm, cm);
#pragma unroll
                    for (int m = 0; m < 4; m++) {
                        int p = lane + 32*m;
                        int idx = li*128 + p;
                        u64 ho2 = pkf2(hOp[p]);
                        u64 te2 = pkf2(teOp[p]);
                        u64 tEo = pkf2(smTE2[idx]);
                        u64 a   = fma2(mnte2, ho2, mul2(nh2, te2));
                        u64 tEn = fma2(c_sE2, a, mul2(c_osE2, tEo));
                        smTE2[idx] = upk2(tEn);
                        u64 dUn = fma2(c_osU2, dUr2[is][m], mul2(cm2, tEn));
                        float2 dv = upk2(dUn);
                        bool need = fmaxf(fabsf(dv.x), fabsf(dv.y)) > bmin;
                        if (__any_sync(0xffffffffu, need)) {   // rare exact clamp
                            if (need) {
                                int j0 = (i << 8) + 2*p;
                                float2 hl0 = __ldg(&g_hilo[j0]);
                                float2 hl1 = __ldg(&g_hilo[j0 + 1]);
                                dv.x = fmaxf(fminf(dv.x, hl0.x), hl0.y);
                                dv.y = fmaxf(fminf(dv.y, hl1.x), hl1.y);
                            }
                            dUn = pk2(dv.x, dv.y);
                        }
                        dUr2[is][m] = dUn;
                        acc2 = fma2(dUn, hnj2[m], acc2);
                    }
                } else {
#pragma unroll
                    for (int m = 0; m < 4; m++) {
                        int p = lane + 32*m;
                        int idx = li*128 + p;
                        int j0 = (i << 8) + 2*p;
                        float2 tE2 = smTE2[idx];
                        float2 se2 = *(const float2*)(g_sE + j0);
                        float2 su2 = *(const float2*)(g_sU + j0);
                        float2 ra2 = *(const float2*)(g_ra + j0);
                        float2 ho = hOp[p], te = teOp[p];
                        float2 dUo = upk2(dUr2[is][m]);
                        float ax = nh_i*te.x - nte_i*ho.x;
                        float ay = nh_i*te.y - nte_i*ho.y;
                        float tEnx = (1.f - se2.x)*tE2.x + se2.x*ax;
                        float tEny = (1.f - se2.y)*tE2.y + se2.y*ay;
                        smTE2[idx] = make_float2(tEnx, tEny);
                        float dUx = (1.f - su2.x)*dUo.x + su2.x*mod_i*tEnx;
                        float dUy = (1.f - su2.y)*dUo.y + su2.y*mod_i*tEny;
                        float2 hl0 = __ldg(&g_hilo[j0]);
                        float2 hl1 = __ldg(&g_hilo[j0 + 1]);
                        dUx = fmaxf(fminf(dUx, hl0.x), hl0.y);
                        dUy = fmaxf(fminf(dUy, hl1.x), hl1.y);
                        dUr2[is][m] = pk2(dUx, dUy);
                        acc2 = fma2(pk2(ra2.x*dUx, ra2.y*dUy), hnj2[m], acc2);
                    }
                }
                float2 af = upk2(acc2);
                float acc = af.x + af.y;
#pragma unroll
                for (int o = 16; o > 0; o >>= 1) acc += __shfl_xor_sync(0xffffffffu, acc, o);
                if (lane == 0) {
                    float zi = UNIF ? ra0 * acc : acc;
                    sm[zW + i] = zi;
                    st_remote(smb + 4u*(zW + i), peer, zi);
                }
                // finish Wh row q=is
                if (doWh) {
                    float4 hv0 = hv4[lane];
                    float4 hv1 = hv4[lane + 32];
                    u64 wa = fma2(pk2(wv0.x, wv0.y), pk2(hv0.x, hv0.y), pk2(0.f, 0.f));
                    wa = fma2(pk2(wv0.z, wv0.w), pk2(hv0.z, hv0.w), wa);
                    wa = fma2(pk2(wv1.x, wv1.y), pk2(hv1.x, hv1.y), wa);
                    wa = fma2(pk2(wv1.z, wv1.w), pk2(hv1.z, hv1.w), wa);
                    float2 wf = upk2(wa);
                    float wacc = wf.x + wf.y;
#pragma unroll
                    for (int o = 16; o > 0; o >>= 1) wacc += __shfl_xor_sync(0xffffffffu, wacc, o);
                    if (lane == 0) {
                        int k = kbase + is;
                        float vv = wacc + __ldg(&h2h_b[k]);
                        sm[whW + k] = vv;
                        st_remote(smb + 4u*(whW + k), peer, vv);
                    }
                }
            }
            // Wh tail rows q=8,9
            if (doWh) {
#pragma unroll
                for (int q = 8; q < 10; q++) {
                    int k = kbase + q;
                    const float4* wr = (const float4*)(h2h_w + (size_t)k*H_);
                    float4 wv0 = __ldg(&wr[lane]);
                    float4 wv1 = __ldg(&wr[lane + 32]);
                    float4 hv0 = hv4[lane];
                    float4 hv1 = hv4[lane + 32];
                    u64 wa = fma2(pk2(wv0.x, wv0.y), pk2(hv0.x, hv0.y), pk2(0.f, 0.f));
                    wa = fma2(pk2(wv0.z, wv0.w), pk2(hv0.z, hv0.w), wa);
                    wa = fma2(pk2(wv1.x, wv1.y), pk2(hv1.x, hv1.y), wa);
                    wa = fma2(pk2(wv1.z, wv1.w), pk2(hv1.z, hv1.w), wa);
                    float2 wf = upk2(wa);
                    float wacc = wf.x + wf.y;
#pragma unroll
                    for (int o = 16; o > 0; o >>= 1) wacc += __shfl_xor_sync(0xffffffffu, wacc, o);
                    if (lane == 0) {
                        float vv = wacc + __ldg(&h2h_b[k]);
                        sm[whW + k] = vv;
                        st_remote(smb + 4u*(whW + k), peer, vv);
                    }
                }
            }
        }
        CLUSTER_SYNC();   // one sync/step: z + Wh(t+1) exchanged
    }

    // ---------- epilogue ----------
#pragma unroll
    for (int is = 0; is < 8; is++) {
        int li = w*8 + is;
        int i  = i0 + li;
        float2* drow = (float2*)(o_dU + (size_t)(b*H_ + i)*H_);
        float2* trow = (float2*)(o_tE + (size_t)(b*H_ + i)*H_);
#pragma unroll
        for (int m = 0; m < 4; m++) {
            int p = lane + 32*m;
            drow[p] = upk2(dUr2[is][m]);
            trow[p] = smTE2[li*128 + p];
        }
    }
    if (tid < 128) {
        int idx = i0 + tid;
        o_v[b*H_ + idx]  = sm[SM_V + idx];
        o_h[b*H_ + idx]  = sm[SM_H + idx];    // T even -> final in buffer 0
        o_te[b*H_ + idx] = sm[SM_TEV + idx];
    }
}

__global__ void __launch_bounds__(NTHR, 1) __cluster_dims__(2, 1, 1)
sgru_cluster(const float* __restrict__ h0,  const float* __restrict__ v0,
             const float* __restrict__ dU0, const float* __restrict__ te0,
             const float* __restrict__ tE0,
             const float* __restrict__ h2h_w, const float* __restrict__ h2h_b,
             const float* __restrict__ lnh_g, const float* __restrict__ lnh_b,
             const float* __restrict__ mod2h, const float* __restrict__ tau_v,
             float* __restrict__ outp)
{
    extern __shared__ float sm[];
    const int tid  = threadIdx.x;
    const int w    = tid >> 5;
    const int lane = tid & 31;
    const int b    = blockIdx.x >> 1;
    const int rank = (int)ctarank();
    const uint32_t smb = s2u(sm);

    if (g_unif) run_all<true >(sm, smb, b, rank, tid, w, lane, h0, v0, dU0, te0, tE0,
                               h2h_w, h2h_b, lnh_g, lnh_b, mod2h, tau_v, outp);
    else        run_all<false>(sm, smb, b, rank, tid, w, lane, h0, v0, dU0, te0, tE0,
                               h2h_w, h2h_b, lnh_g, lnh_b, mod2h, tau_v, outp);
}

extern "C" void kernel_launch(void* const* d_in, const int* in_sizes, int n_in,
                              void* d_out, int out_size) {
    const float* x      = (const float*)d_in[0];
    const float* h0     = (const float*)d_in[1];
    const float* v0     = (const float*)d_in[2];
    const float* dU0    = (const float*)d_in[3];
    const float* te0    = (const float*)d_in[4];
    const float* tE0    = (const float*)d_in[5];
    const float* x2h_w  = (const float*)d_in[6];
    const float* x2h_b  = (const float*)d_in[7];
    const float* h2h_w  = (const float*)d_in[8];
    const float* h2h_b  = (const float*)d_in[9];
    const float* lnx_g  = (const float*)d_in[10];
    const float* lnx_b  = (const float*)d_in[11];
    const float* lnh_g  = (const float*)d_in[12];
    const float* lnh_b  = (const float*)d_in[13];
    const float* alpha  = (const float*)d_in[14];
    const float* mod2h  = (const float*)d_in[15];
    const float* tau_v  = (const float*)d_in[16];
    const float* tau_U  = (const float*)d_in[17];
    const float* tau_E  = (const float*)d_in[18];

    static int smem_set = 0;
    if (!smem_set) {
        cudaFuncSetAttribute(sgru_cluster, cudaFuncAttributeMaxDynamicSharedMemorySize, SM_BYTES);
        smem_set = 1;
    }

    k_init<<<1, 1>>>();
    k_prep<<<H_*H_/256, 256>>>(alpha, tau_U, tau_E, h2h_w, mod2h);
    k_wx<<<B_, 640>>>(x, x2h_w, x2h_b, lnx_g, lnx_b);
    sgru_cluster<<<2*B_, NTHR, SM_BYTES>>>(h0, v0, dU0, te0, tE0,
                                           h2h_w, h2h_b, lnh_g, lnh_b,
                                           mod2h, tau_v, (float*)d_out);
}

// round 10
// speedup vs baseline: 1.3977x; 1.1982x over previous
#include <cuda_runtime.h>
#include <math.h>
#include <stdint.h>

#define T_ 24
#define B_ 64
#define I_ 128
#define H_ 256
#define R_ 64
#define HR 320
#define NTHR 512
#define LN_EPS 1e-5f

// ---- smem float offsets ----
#define SM_TE   0        // 128 rows * 128 float2 = 32768 floats
#define SM_H    32768    // 2*256 ping-pong h
#define SM_TEV  33280    // 2*256 ping-pong te
#define SM_Z    33792    // 2*256 ping-pong z
#define SM_V    34304    // 256
#define SM_MOD  34560    // 256
#define SM_WH   34816    // 2*320 ping-pong Wh
#define SM_SV   35456    // 256
#define SM_U    35712    // 64
#define SM_RED  35776    // 64
#define SM_ZP   35840    // 128 rows * stride 36 = 4608
#define SM_WHP  40448    // 160 rows * stride 36 = 5760
#define SM_TOT  46208
#define SM_BYTES (SM_TOT*4)

// ---- global scratch ----
__device__ float  g_Wx[T_*B_*HR];
__device__ float2 g_hilo[H_*H_];
__device__ float  g_ra[H_*H_];
__device__ float  g_sU[H_*H_];
__device__ float  g_sE[H_*H_];
__device__ int    g_unif = 1;
__device__ int    g_munif = 1;
__device__ int    g_bmin_bits = 0x7f7fffff;
__device__ float  g_ra0, g_sU0, g_sE0, g_m2h0;

typedef unsigned long long u64;

__device__ __forceinline__ float sigmoidf(float x) { return 1.f / (1.f + expf(-x)); }

__device__ __forceinline__ u64 pk2(float lo, float hi) {
    u64 r; asm("mov.b64 %0, {%1, %2};" : "=l"(r) : "f"(lo), "f"(hi)); return r;
}
__device__ __forceinline__ float2 upk2(u64 v) {
    float2 r; asm("mov.b64 {%0, %1}, %2;" : "=f"(r.x), "=f"(r.y) : "l"(v)); return r;
}
__device__ __forceinline__ u64 fma2(u64 a, u64 b, u64 c) {
    u64 r; asm("fma.rn.f32x2 %0, %1, %2, %3;" : "=l"(r) : "l"(a), "l"(b), "l"(c)); return r;
}
__device__ __forceinline__ u64 mul2(u64 a, u64 b) {
    u64 r; asm("mul.rn.f32x2 %0, %1, %2;" : "=l"(r) : "l"(a), "l"(b)); return r;
}
__device__ __forceinline__ u64 pkf2(float2 v) { return pk2(v.x, v.y); }

__device__ __forceinline__ uint32_t s2u(const void* p) {
    uint32_t a;
    asm("{ .reg .u64 t; cvta.to.shared.u64 t, %1; cvt.u32.u64 %0, t; }" : "=r"(a) : "l"(p));
    return a;
}
__device__ __forceinline__ uint32_t ctarank() {
    uint32_t r; asm("mov.u32 %0, %%cluster_ctarank;" : "=r"(r)); return r;
}
__device__ __forceinline__ void st_remote(uint32_t my_addr, uint32_t peer, float v) {
    uint32_t ra;
    asm volatile("mapa.shared::cluster.u32 %0, %1, %2;" : "=r"(ra) : "r"(my_addr), "r"(peer));
    asm volatile("st.shared::cluster.f32 [%0], %1;" :: "r"(ra), "f"(v) : "memory");
}
#define CLUSTER_SYNC() do { \
    asm volatile("barrier.cluster.arrive.aligned;" ::: "memory"); \
    asm volatile("barrier.cluster.wait.aligned;" ::: "memory"); } while (0)

// -------- per-(i,j) constants; warp-reduced atomics (flags statically initialized,
// atomics only tighten -> converged & deterministic across graph replays) --------
__global__ void k_prep(const float* __restrict__ alpha,
                       const float* __restrict__ tauU,
                       const float* __restrict__ tauE,
                       const float* __restrict__ h2h_w,
                       const float* __restrict__ mod2h) {
    int idx = blockIdx.x * blockDim.x + threadIdx.x;   // 0..65535
    int lane = threadIdx.x & 31;
    float a = alpha[idx], u = tauU[idx], e = tauE[idx];
    float ra = fmaxf(a, 0.f);
    g_ra[idx] = ra;
    g_sU[idx] = sigmoidf(u);
    g_sE[idx] = sigmoidf(e);
    float wv = h2h_w[idx];
    float den = ra + 1e-8f;
    float hi = fmaxf(1.f - wv, 0.f) / den;
    float lo = -fmaxf(1.f + wv, 0.f) / den;
    g_hilo[idx] = make_float2(hi, lo);
    float bnd = fminf(hi, -lo);            // >= 0
#pragma unroll
    for (int o = 16; o > 0; o >>= 1) bnd = fminf(bnd, __shfl_xor_sync(0xffffffffu, bnd, o));
    bool eq = (a == alpha[0]) && (u == tauU[0]) && (e == tauE[0]);
    bool alleq = __all_sync(0xffffffffu, eq);
    if (lane == 0) {
        atomicMin(&g_bmin_bits, __float_as_int(bnd));  // bnd >= 0: int order == float order
        if (!alleq) atomicAnd(&g_unif, 0);
    }
    if (idx < H_ * R_) {
        bool meq = (mod2h[idx] == mod2h[0]);
        bool allm = __all_sync(__activemask(), meq);
        if (lane == 0 && !allm) atomicAnd(&g_munif, 0);
    }
    if (idx == 0) {
        g_ra0 = ra; g_sU0 = sigmoidf(u); g_sE0 = sigmoidf(e); g_m2h0 = mod2h[0];
    }
}

// -------- Wx: weight-stationary. Block = batch b; thread-pair owns a row half --------
__global__ void __launch_bounds__(640, 1)
k_wx(const float* __restrict__ x,
     const float* __restrict__ w,
     const float* __restrict__ bias,
     const float* __restrict__ lng,
     const float* __restrict__ lnb) {
    int b = blockIdx.x;
    int tid = threadIdx.x;               // 0..639
    __shared__ float sx[T_*I_];          // 3072
    __shared__ float swh[T_*HR];         // 7680

    for (int idx = tid; idx < T_*I_; idx += 640)
        sx[idx] = x[(idx >> 7)*(B_*I_) + b*I_ + (idx & 127)];

    int k = tid >> 1;                    // row 0..319
    int half = tid & 1;
    const float4* wr = (const float4*)(w + (size_t)k*I_ + half*64);
    float4 wreg[16];
#pragma unroll
    for (int m = 0; m < 16; m++) wreg[m] = __ldg(&wr[m]);
    float bk = bias[k];
    __syncthreads();

    for (int t = 0; t < T_; t++) {
        const float4* xb4 = (const float4*)&sx[t*I_ + half*64];
        float acc = 0.f;
#pragma unroll
        for (int m = 0; m < 16; m++) {
            float4 wv = wreg[m];
            float4 xv = xb4[m];
            acc += wv.x*xv.x + wv.y*xv.y + wv.z*xv.z + wv.w*xv.w;
        }
        acc += __shfl_xor_sync(0xffffffffu, acc, 1);
        if (half == 0) swh[t*HR + k] = acc + bk;
    }
    __syncthreads();

    int wid = tid >> 5, lane = tid & 31;
    for (int t = wid; t < T_; t += 20) {
        float vv[10]; float s = 0.f, s2 = 0.f;
#pragma unroll
        for (int e = 0; e < 10; e++) {
            vv[e] = swh[t*HR + lane + 32*e];
            s += vv[e]; s2 += vv[e]*vv[e];
        }
#pragma unroll
        for (int o = 16; o > 0; o >>= 1) {
            s  += __shfl_xor_sync(0xffffffffu, s,  o);
            s2 += __shfl_xor_sync(0xffffffffu, s2, o);
        }
        float mu  = s * (1.f/HR);
        float inv = rsqrtf(s2 * (1.f/HR) - mu*mu + LN_EPS);
#pragma unroll
        for (int e = 0; e < 10; e++) {
            int k2 = lane + 32*e;
            g_Wx[(t*B_ + b)*HR + k2] = (vv[e] - mu) * inv * __ldg(&lng[k2]) + __ldg(&lnb[k2]);
        }
    }
}

// ================= main per-batch cluster kernel =================
template<bool UNIF>
__device__ __forceinline__ void run_all(
    float* sm, uint32_t smb, int b, int rank, int tid, int w, int lane,
    const float* __restrict__ h0,  const float* __restrict__ v0,
    const float* __restrict__ dU0, const float* __restrict__ te0,
    const float* __restrict__ tE0,
    const float* __restrict__ h2h_w, const float* __restrict__ h2h_b,
    const float* __restrict__ lnh_g, const float* __restrict__ lnh_b,
    const float* __restrict__ mod2h, const float* __restrict__ tau_v,
    float* __restrict__ outp)
{
    float* o_v   = outp;
    float* o_h   = outp + 16384;
    float* o_dU  = outp + 32768;
    float* o_te  = outp + 4227072;
    float* o_tE  = outp + 4243456;
    float* o_out = outp + 8437760;

    const uint32_t peer = rank ^ 1u;
    const int i0 = rank * 128;
    const int kbase = rank*160 + w*10;
    const bool munif = (g_munif != 0);
    const float m2h0 = g_m2h0;
    const float ra0 = g_ra0, sU0 = g_sU0, sE0 = g_sE0;
    const float bmin = __int_as_float(g_bmin_bits);
    const u64 c_sE2  = pk2(sE0, sE0);
    const u64 c_osE2 = pk2(1.f - sE0, 1.f - sE0);
    const u64 c_osU2 = pk2(1.f - sU0, 1.f - sU0);
    float2* smTE2 = (float2*)sm;   // SM_TE == 0

    // ---------- prologue ----------
    float r_lng = 0.f, r_lnb = 0.f;
    if (tid < HR) { r_lng = lnh_g[tid]; r_lnb = lnh_b[tid]; }

    if (tid < H_) {
        sm[SM_SV + tid]  = sigmoidf(tau_v[tid]);
        sm[SM_H + tid]   = h0[b*H_ + tid];
        sm[SM_TEV + tid] = te0[b*H_ + tid];
        sm[SM_V + tid]   = v0[b*H_ + tid];
    }
    u64 dUr2[8][4];
    {
        const float2* h0p = (const float2*)(h0 + b*H_);
        u64 h0j2[4];
#pragma unroll
        for (int m = 0; m < 4; m++) h0j2[m] = pkf2(h0p[lane + 32*m]);
#pragma unroll
        for (int is = 0; is < 8; is++) {
            int li = w*8 + is;
            int i  = i0 + li;
            const float2* drow = (const float2*)(dU0 + (size_t)(b*H_ + i)*H_);
            const float2* trow = (const float2*)(tE0 + (size_t)(b*H_ + i)*H_);
            u64 acc2 = pk2(0.f, 0.f);
#pragma unroll
            for (int m = 0; m < 4; m++) {
                int p = lane + 32*m;
                float2 d = drow[p];
                smTE2[li*128 + p] = trow[p];
                u64 dv = pkf2(d);
                dUr2[is][m] = dv;
                if (UNIF) acc2 = fma2(dv, h0j2[m], acc2);
                else {
                    const float2* rap = (const float2*)(g_ra + (size_t)i*H_);
                    acc2 = fma2(mul2(pkf2(rap[p]), dv), h0j2[m], acc2);
                }
            }
            float2 af = upk2(acc2);
            float acc = af.x + af.y;
#pragma unroll
            for (int o = 16; o > 0; o >>= 1) acc += __shfl_xor_sync(0xffffffffu, acc, o);
            if (lane == 0) {
                float zi = UNIF ? ra0 * acc : acc;
                sm[SM_Z + i] = zi;
                st_remote(smb + 4u*(SM_Z + i), peer, zi);
            }
        }
    }
    __syncthreads();
    // Wh(0) from h0 (buffer 0)
    {
        const float4* hv4 = (const float4*)&sm[SM_H];
#pragma unroll
        for (int q = 0; q < 10; q++) {
            int k = kbase + q;
            const float4* wr = (const float4*)(h2h_w + (size_t)k*H_);
            float4 wv0 = __ldg(&wr[lane]);
            float4 wv1 = __ldg(&wr[lane + 32]);
            float4 hv0 = hv4[lane];
            float4 hv1 = hv4[lane + 32];
            u64 acc2 = fma2(pk2(wv0.x, wv0.y), pk2(hv0.x, hv0.y), pk2(0.f, 0.f));
            acc2 = fma2(pk2(wv0.z, wv0.w), pk2(hv0.z, hv0.w), acc2);
            acc2 = fma2(pk2(wv1.x, wv1.y), pk2(hv1.x, hv1.y), acc2);
            acc2 = fma2(pk2(wv1.z, wv1.w), pk2(hv1.z, hv1.w), acc2);
            float2 af = upk2(acc2);
            float acc = af.x + af.y;
#pragma unroll
            for (int o = 16; o > 0; o >>= 1) acc += __shfl_xor_sync(0xffffffffu, acc, o);
            if (lane == 0) {
                float vv = acc + __ldg(&h2h_b[k]);
                sm[SM_WH + k] = vv;
                st_remote(smb + 4u*(SM_WH + k), peer, vv);
            }
        }
    }
    CLUSTER_SYNC();

    // ---------- time loop ----------
    for (int t = 0; t < T_; t++) {
        const int hO  = SM_H   + (t & 1)*H_;
        const int hN  = SM_H   + ((t+1) & 1)*H_;
        const int teO = SM_TEV + (t & 1)*H_;
        const int teN = SM_TEV + ((t+1) & 1)*H_;
        const int zR  = SM_Z   + (t & 1)*H_;
        const int zW  = SM_Z   + ((t+1) & 1)*H_;
        const int whR = SM_WH  + (t & 1)*HR;
        const int whW = SM_WH  + ((t+1) & 1)*HR;
        const bool doWh = (t < T_ - 1);

        // ---- small phase (redundant in both CTAs) ----
        float wxv = 0.f;
        if (tid < HR) wxv = __ldg(&g_Wx[(t*B_ + b)*HR + tid]);

        // LN stats: every warp computes redundantly (no cross-warp serialization)
        float mu, inv;
        {
            float s = 0.f, s2 = 0.f;
#pragma unroll
            for (int e = 0; e < 10; e++) {
                float vv = sm[whR + lane + 32*e];
                s += vv; s2 += vv*vv;
            }
#pragma unroll
            for (int o = 16; o > 0; o >>= 1) {
                s  += __shfl_xor_sync(0xffffffffu, s,  o);
                s2 += __shfl_xor_sync(0xffffffffu, s2, o);
            }
            mu  = s * (1.f/HR);
            inv = rsqrtf(s2 * (1.f/HR) - mu*mu + LN_EPS);
        }
        float whv = 0.f;
        if (tid < HR) {
            whv = (sm[whR + tid] - mu) * inv * r_lng + r_lnb;
            if (tid >= H_) {
                float uval = fmaxf(wxv + whv, 0.f);
                sm[SM_U + tid - H_] = uval;
                if (munif) {   // warps 8,9: fold mod partial sums
#pragma unroll
                    for (int o = 16; o > 0; o >>= 1)
                        uval += __shfl_xor_sync(0xffffffffu, uval, o);
                    if (lane == 0) sm[SM_RED + 40 + (w - 8)] = uval;
                }
            }
        }
        __syncthreads();
        if (tid < H_) {
            float sv = sm[SM_SV + tid];
            float dv = wxv + whv + sm[zR + tid];
            float vo = sm[SM_V + tid];
            float vn = (1.f - sv) * vo + sv * dv;
            sm[SM_V + tid] = vn;
            float nh = fmaxf(vn, 0.f);
            sm[hN + tid] = nh;
            float teo = sm[teO + tid];
            sm[teN + tid] = (1.f - sv) * teo + sv * sm[hO + tid];
            if ((tid >> 7) == rank) o_out[(t*B_ + b)*H_ + tid] = nh;
            float mv;
            if (munif) {
                mv = m2h0 * (sm[SM_RED + 40] + sm[SM_RED + 41]);
            } else {
                mv = 0.f;
                const float4* mr = (const float4*)(mod2h + tid*R_);
#pragma unroll
                for (int r = 0; r < 16; r++) {
                    float4 m4 = __ldg(mr + r);
                    mv += m4.x*sm[SM_U + 4*r] + m4.y*sm[SM_U + 4*r+1]
                        + m4.z*sm[SM_U + 4*r+2] + m4.w*sm[SM_U + 4*r+3];
                }
            }
            sm[SM_MOD + tid] = mv;
        }
        __syncthreads();

        // ---- merged phase: big update (t) + Wh(t+1); partials to smem ----
        {
            const float2* hOp  = (const float2*)&sm[hO];
            const float2* teOp = (const float2*)&sm[teO];
            const float2* hNp  = (const float2*)&sm[hN];
            const float4* hv4  = (const float4*)&sm[hN];
            u64 hnj2[4];
#pragma unroll
            for (int m = 0; m < 4; m++) hnj2[m] = pkf2(hNp[lane + 32*m]);

#pragma unroll
            for (int is = 0; is < 8; is++) {
                float4 wv0, wv1;
                if (doWh) {
                    const float4* wr = (const float4*)(h2h_w + (size_t)(kbase + is)*H_);
                    wv0 = __ldg(&wr[lane]);
                    wv1 = __ldg(&wr[lane + 32]);
                }
                int li = w*8 + is;
                int i  = i0 + li;
                float nh_i  = sm[hN + i];
                float nte_i = sm[teN + i];
                float mod_i = sm[SM_MOD + i];
                u64 nh2   = pk2(nh_i, nh_i);
                u64 mnte2 = pk2(-nte_i, -nte_i);
                u64 acc2  = pk2(0.f, 0.f);
                if (UNIF) {
                    float cm = sU0 * mod_i;
                    u64 cm2 = pk2(cm, cm);
#pragma unroll
                    for (int m = 0; m < 4; m++) {
                        int p = lane + 32*m;
                        int idx = li*128 + p;
                        u64 ho2 = pkf2(hOp[p]);
                        u64 te2 = pkf2(teOp[p]);
                        u64 tEo = pkf2(smTE2[idx]);
                        u64 a   = fma2(mnte2, ho2, mul2(nh2, te2));
                        u64 tEn = fma2(c_sE2, a, mul2(c_osE2, tEo));
                        smTE2[idx] = upk2(tEn);
                        u64 dUn = fma2(c_osU2, dUr2[is][m], mul2(cm2, tEn));
                        float2 dv = upk2(dUn);
                        bool need = fmaxf(fabsf(dv.x), fabsf(dv.y)) > bmin;
                        if (__any_sync(0xffffffffu, need)) {   // rare exact clamp
                            if (need) {
                                int j0 = (i << 8) + 2*p;
                                float2 hl0 = __ldg(&g_hilo[j0]);
                                float2 hl1 = __ldg(&g_hilo[j0 + 1]);
                                dv.x = fmaxf(fminf(dv.x, hl0.x), hl0.y);
                                dv.y = fmaxf(fminf(dv.y, hl1.x), hl1.y);
                            }
                            dUn = pk2(dv.x, dv.y);
                        }
                        dUr2[is][m] = dUn;
                        acc2 = fma2(dUn, hnj2[m], acc2);
                    }
                } else {
#pragma unroll
                    for (int m = 0; m < 4; m++) {
                        int p = lane + 32*m;
                        int idx = li*128 + p;
                        int j0 = (i << 8) + 2*p;
                        float2 tE2 = smTE2[idx];
                        float2 se2 = *(const float2*)(g_sE + j0);
                        float2 su2 = *(const float2*)(g_sU + j0);
                        float2 ra2 = *(const float2*)(g_ra + j0);
                        float2 ho = hOp[p], te = teOp[p];
                        float2 dUo = upk2(dUr2[is][m]);
                        float ax = nh_i*te.x - nte_i*ho.x;
                        float ay = nh_i*te.y - nte_i*ho.y;
                        float tEnx = (1.f - se2.x)*tE2.x + se2.x*ax;
                        float tEny = (1.f - se2.y)*tE2.y + se2.y*ay;
                        smTE2[idx] = make_float2(tEnx, tEny);
                        float dUx = (1.f - su2.x)*dUo.x + su2.x*mod_i*tEnx;
                        float dUy = (1.f - su2.y)*dUo.y + su2.y*mod_i*tEny;
                        float2 hl0 = __ldg(&g_hilo[j0]);
                        float2 hl1 = __ldg(&g_hilo[j0 + 1]);
                        dUx = fmaxf(fminf(dUx, hl0.x), hl0.y);
                        dUy = fmaxf(fminf(dUy, hl1.x), hl1.y);
                        dUr2[is][m] = pk2(dUx, dUy);
                        acc2 = fma2(pk2(ra2.x*dUx, ra2.y*dUy), hnj2[m], acc2);
                    }
                }
                float2 af = upk2(acc2);
                sm[SM_ZP + li*36 + lane] = af.x + af.y;    // z partial (tree deferred)
                if (doWh) {
                    float4 hv0 = hv4[lane];
                    float4 hv1 = hv4[lane + 32];
                    u64 wa = fma2(pk2(wv0.x, wv0.y), pk2(hv0.x, hv0.y), pk2(0.f, 0.f));
                    wa = fma2(pk2(wv0.z, wv0.w), pk2(hv0.z, hv0.w), wa);
                    wa = fma2(pk2(wv1.x, wv1.y), pk2(hv1.x, hv1.y), wa);
                    wa = fma2(pk2(wv1.z, wv1.w), pk2(hv1.z, hv1.w), wa);
                    float2 wf = upk2(wa);
                    sm[SM_WHP + (w*10 + is)*36 + lane] = wf.x + wf.y;
                }
            }
            if (doWh) {
#pragma unroll
                for (int q = 8; q < 10; q++) {
                    int k = kbase + q;
                    const float4* wr = (const float4*)(h2h_w + (size_t)k*H_);
                    float4 wv0 = __ldg(&wr[lane]);
                    float4 wv1 = __ldg(&wr[lane + 32]);
                    float4 hv0 = hv4[lane];
                    float4 hv1 = hv4[lane + 32];
                    u64 wa = fma2(pk2(wv0.x, wv0.y), pk2(hv0.x, hv0.y), pk2(0.f, 0.f));
                    wa = fma2(pk2(wv0.z, wv0.w), pk2(hv0.z, hv0.w), wa);
                    wa = fma2(pk2(wv1.x, wv1.y), pk2(hv1.x, hv1.y), wa);
                    wa = fma2(pk2(wv1.z, wv1.w), pk2(hv1.z, hv1.w), wa);
                    float2 wf = upk2(wa);
                    sm[SM_WHP + (w*10 + q)*36 + lane] = wf.x + wf.y;
                }
            }
        }
        __syncthreads();

        // ---- reduction pass: all z rows + all Wh rows in parallel ----
        {
            int row = tid >> 2;            // 0..127
            int sub = tid & 3;
            const float4* zp4 = (const float4*)&sm[SM_ZP + row*36 + sub*8];
            float4 a0 = zp4[0], a1 = zp4[1];
            float s = (a0.x + a0.y) + (a0.z + a0.w) + (a1.x + a1.y) + (a1.z + a1.w);
            s += __shfl_xor_sync(0xffffffffu, s, 2);
            s += __shfl_xor_sync(0xffffffffu, s, 1);
            if (sub == 0) {
                int i = i0 + row;
                float zi = UNIF ? ra0 * s : s;
                sm[zW + i] = zi;
                st_remote(smb + 4u*(zW + i), peer, zi);
            }
            if (doWh) {
                int row2 = tid >> 1;       // 0..255
                int sub2 = tid & 1;
                if (row2 < 160) {          // warps 0..9 fully active (warp-uniform)
                    const float4* wp4 = (const float4*)&sm[SM_WHP + row2*36 + sub2*16];
                    float4 b0 = wp4[0], b1 = wp4[1], b2 = wp4[2], b3 = wp4[3];
                    float sw = ((b0.x + b0.y) + (b0.z + b0.w)) + ((b1.x + b1.y) + (b1.z + b1.w))
                             + ((b2.x + b2.y) + (b2.z + b2.w)) + ((b3.x + b3.y) + (b3.z + b3.w));
                    sw += __shfl_xor_sync(0xffffffffu, sw, 1);
                    if (sub2 == 0) {
                        int k = rank*160 + row2;
                        float vv = sw + __ldg(&h2h_b[k]);
                        sm[whW + k] = vv;
                        st_remote(smb + 4u*(whW + k), peer, vv);
                    }
                }
            }
        }
        CLUSTER_SYNC();   // one sync/step: z + Wh(t+1) exchanged
    }

    // ---------- epilogue ----------
#pragma unroll
    for (int is = 0; is < 8; is++) {
        int li = w*8 + is;
        int i  = i0 + li;
        float2* drow = (float2*)(o_dU + (size_t)(b*H_ + i)*H_);
        float2* trow = (float2*)(o_tE + (size_t)(b*H_ + i)*H_);
#pragma unroll
        for (int m = 0; m < 4; m++) {
            int p = lane + 32*m;
            drow[p] = upk2(dUr2[is][m]);
            trow[p] = smTE2[li*128 + p];
        }
    }
    if (tid < 128) {
        int idx = i0 + tid;
        o_v[b*H_ + idx]  = sm[SM_V + idx];
        o_h[b*H_ + idx]  = sm[SM_H + idx];    // T even -> final in buffer 0
        o_te[b*H_ + idx] = sm[SM_TEV + idx];
    }
}

__global__ void __launch_bounds__(NTHR, 1) __cluster_dims__(2, 1, 1)
sgru_cluster(const float* __restrict__ h0,  const float* __restrict__ v0,
             const float* __restrict__ dU0, const float* __restrict__ te0,
             const float* __restrict__ tE0,
             const float* __restrict__ h2h_w, const float* __restrict__ h2h_b,
             const float* __restrict__ lnh_g, const float* __restrict__ lnh_b,
             const float* __restrict__ mod2h, const float* __restrict__ tau_v,
             float* __restrict__ outp)
{
    extern __shared__ float sm[];
    const int tid  = threadIdx.x;
    const int w    = tid >> 5;
    const int lane = tid & 31;
    const int b    = blockIdx.x >> 1;
    const int rank = (int)ctarank();
    const uint32_t smb = s2u(sm);

    if (g_unif) run_all<true >(sm, smb, b, rank, tid, w, lane, h0, v0, dU0, te0, tE0,
                               h2h_w, h2h_b, lnh_g, lnh_b, mod2h, tau_v, outp);
    else        run_all<false>(sm, smb, b, rank, tid, w, lane, h0, v0, dU0, te0, tE0,
                               h2h_w, h2h_b, lnh_g, lnh_b, mod2h, tau_v, outp);
}

extern "C" void kernel_launch(void* const* d_in, const int* in_sizes, int n_in,
                              void* d_out, int out_size) {
    const float* x      = (const float*)d_in[0];
    const float* h0     = (const float*)d_in[1];
    const float* v0     = (const float*)d_in[2];
    const float* dU0    = (const float*)d_in[3];
    const float* te0    = (const float*)d_in[4];
    const float* tE0    = (const float*)d_in[5];
    const float* x2h_w  = (const float*)d_in[6];
    const float* x2h_b  = (const float*)d_in[7];
    const float* h2h_w  = (const float*)d_in[8];
    const float* h2h_b  = (const float*)d_in[9];
    const float* lnx_g  = (const float*)d_in[10];
    const float* lnx_b  = (const float*)d_in[11];
    const float* lnh_g  = (const float*)d_in[12];
    const float* lnh_b  = (const float*)d_in[13];
    const float* alpha  = (const float*)d_in[14];
    const float* mod2h  = (const float*)d_in[15];
    const float* tau_v  = (const float*)d_in[16];
    const float* tau_U  = (const float*)d_in[17];
    const float* tau_E  = (const float*)d_in[18];

    static int smem_set = 0;
    if (!smem_set) {
        cudaFuncSetAttribute(sgru_cluster, cudaFuncAttributeMaxDynamicSharedMemorySize, SM_BYTES);
        smem_set = 1;
    }

    k_prep<<<H_*H_/256, 256>>>(alpha, tau_U, tau_E, h2h_w, mod2h);
    k_wx<<<B_, 640>>>(x, x2h_w, x2h_b, lnx_g, lnx_b);
    sgru_cluster<<<2*B_, NTHR, SM_BYTES>>>(h0, v0, dU0, te0, tE0,
                                           h2h_w, h2h_b, lnh_g, lnh_b,
                                           mod2h, tau_v, (float*)d_out);
}

// round 11
// speedup vs baseline: 1.4500x; 1.0374x over previous
#include <cuda_runtime.h>
#include <math.h>
#include <stdint.h>

#define T_ 24
#define B_ 64
#define I_ 128
#define H_ 256
#define R_ 64
#define HR 320
#define NTHR 512
#define LN_EPS 1e-5f

// ---- smem float offsets ----
#define SM_TE   0        // 128 rows * 128 float2 = 32768 floats
#define SM_H    32768    // 2*256 ping-pong h
#define SM_TEV  33280    // 2*256 ping-pong te
#define SM_Z    33792    // 2*256 ping-pong z
#define SM_V    34304    // 256
#define SM_MOD  34560    // 256
#define SM_WH   34816    // 2*320 ping-pong Wh
#define SM_SV   35456    // 256
#define SM_U    35712    // 64
#define SM_RED  35776    // 64
#define SM_ZP   35840    // 128 rows * stride 36 = 4608
#define SM_WHP  40448    // 160 rows * stride 36 = 5760
#define SM_TOT  46208
#define SM_BYTES (SM_TOT*4)

// ---- global scratch ----
__device__ float  g_Wx[T_*B_*HR];
__device__ float2 g_hilo[H_*H_];
__device__ float  g_ra[H_*H_];
__device__ float  g_sU[H_*H_];
__device__ float  g_sE[H_*H_];
__device__ int    g_unif = 1;
__device__ int    g_munif = 1;
__device__ int    g_bmin_bits = 0x7f7fffff;
__device__ float  g_ra0, g_sU0, g_sE0, g_m2h0;

typedef unsigned long long u64;

__device__ __forceinline__ float sigmoidf(float x) { return 1.f / (1.f + expf(-x)); }

__device__ __forceinline__ u64 pk2(float lo, float hi) {
    u64 r; asm("mov.b64 %0, {%1, %2};" : "=l"(r) : "f"(lo), "f"(hi)); return r;
}
__device__ __forceinline__ float2 upk2(u64 v) {
    float2 r; asm("mov.b64 {%0, %1}, %2;" : "=f"(r.x), "=f"(r.y) : "l"(v)); return r;
}
__device__ __forceinline__ u64 fma2(u64 a, u64 b, u64 c) {
    u64 r; asm("fma.rn.f32x2 %0, %1, %2, %3;" : "=l"(r) : "l"(a), "l"(b), "l"(c)); return r;
}
__device__ __forceinline__ u64 mul2(u64 a, u64 b) {
    u64 r; asm("mul.rn.f32x2 %0, %1, %2;" : "=l"(r) : "l"(a), "l"(b)); return r;
}
__device__ __forceinline__ u64 pkf2(float2 v) { return pk2(v.x, v.y); }

__device__ __forceinline__ uint32_t s2u(const void* p) {
    uint32_t a;
    asm("{ .reg .u64 t; cvta.to.shared.u64 t, %1; cvt.u32.u64 %0, t; }" : "=r"(a) : "l"(p));
    return a;
}
__device__ __forceinline__ uint32_t ctarank() {
    uint32_t r; asm("mov.u32 %0, %%cluster_ctarank;" : "=r"(r)); return r;
}
__device__ __forceinline__ void st_remote(uint32_t my_addr, uint32_t peer, float v) {
    uint32_t ra;
    asm volatile("mapa.shared::cluster.u32 %0, %1, %2;" : "=r"(ra) : "r"(my_addr), "r"(peer));
    asm volatile("st.shared::cluster.f32 [%0], %1;" :: "r"(ra), "f"(v) : "memory");
}
#define CLUSTER_SYNC() do { \
    asm volatile("barrier.cluster.arrive.aligned;" ::: "memory"); \
    asm volatile("barrier.cluster.wait.aligned;" ::: "memory"); } while (0)

// -------- per-element prep (warp-reduced atomics; flags statically initialized;
// atomics only tighten -> converged & deterministic across graph replays) --------
__device__ __forceinline__ void prep_elem(int idx, int lane,
                                          const float* __restrict__ alpha,
                                          const float* __restrict__ tauU,
                                          const float* __restrict__ tauE,
                                          const float* __restrict__ h2h_w,
                                          const float* __restrict__ mod2h) {
    float a = alpha[idx], u = tauU[idx], e = tauE[idx];
    float ra = fmaxf(a, 0.f);
    g_ra[idx] = ra;
    g_sU[idx] = sigmoidf(u);
    g_sE[idx] = sigmoidf(e);
    float wv = h2h_w[idx];
    float den = ra + 1e-8f;
    float hi = fmaxf(1.f - wv, 0.f) / den;
    float lo = -fmaxf(1.f + wv, 0.f) / den;
    g_hilo[idx] = make_float2(hi, lo);
    float bnd = fminf(hi, -lo);            // >= 0
#pragma unroll
    for (int o = 16; o > 0; o >>= 1) bnd = fminf(bnd, __shfl_xor_sync(0xffffffffu, bnd, o));
    bool eq = (a == alpha[0]) && (u == tauU[0]) && (e == tauE[0]);
    bool alleq = __all_sync(0xffffffffu, eq);
    if (lane == 0) {
        atomicMin(&g_bmin_bits, __float_as_int(bnd));  // bnd >= 0: int order == float order
        if (!alleq) atomicAnd(&g_unif, 0);
    }
    if (idx < H_ * R_) {                    // warp-uniform (1024-aligned blocks)
        bool meq = (mod2h[idx] == mod2h[0]);
        bool allm = __all_sync(0xffffffffu, meq);
        if (lane == 0 && !allm) atomicAnd(&g_munif, 0);
    }
    if (idx == 0) {
        g_ra0 = ra; g_sU0 = sigmoidf(u); g_sE0 = sigmoidf(e); g_m2h0 = mod2h[0];
    }
}

// -------- fused aux: prep (1024 elems/block) + weight-stationary Wx --------
__global__ void __launch_bounds__(640, 1)
k_aux(const float* __restrict__ x,
      const float* __restrict__ w,
      const float* __restrict__ bias,
      const float* __restrict__ lng,
      const float* __restrict__ lnb,
      const float* __restrict__ alpha,
      const float* __restrict__ tauU,
      const float* __restrict__ tauE,
      const float* __restrict__ h2h_w,
      const float* __restrict__ mod2h) {
    int b = blockIdx.x;
    int tid = threadIdx.x;               // 0..639
    int lane = tid & 31;
    __shared__ float sx[T_*I_];          // 3072
    __shared__ float swh[T_*HR];         // 7680

    // ---- prep portion: elements [b*1024, (b+1)*1024) ----
    prep_elem(b*1024 + tid, lane, alpha, tauU, tauE, h2h_w, mod2h);
    if (tid < 384) prep_elem(b*1024 + 640 + tid, lane, alpha, tauU, tauE, h2h_w, mod2h);

    // ---- Wx portion ----
    for (int idx = tid; idx < T_*I_; idx += 640)
        sx[idx] = x[(idx >> 7)*(B_*I_) + b*I_ + (idx & 127)];

    int k = tid >> 1;                    // row 0..319
    int half = tid & 1;
    const float4* wr = (const float4*)(w + (size_t)k*I_ + half*64);
    float4 wreg[16];
#pragma unroll
    for (int m = 0; m < 16; m++) wreg[m] = __ldg(&wr[m]);
    float bk = bias[k];
    __syncthreads();

    for (int t = 0; t < T_; t++) {
        const float4* xb4 = (const float4*)&sx[t*I_ + half*64];
        float acc = 0.f;
#pragma unroll
        for (int m = 0; m < 16; m++) {
            float4 wv = wreg[m];
            float4 xv = xb4[m];
            acc += wv.x*xv.x + wv.y*xv.y + wv.z*xv.z + wv.w*xv.w;
        }
        acc += __shfl_xor_sync(0xffffffffu, acc, 1);
        if (half == 0) swh[t*HR + k] = acc + bk;
    }
    __syncthreads();

    int wid = tid >> 5;
    for (int t = wid; t < T_; t += 20) {
        float vv[10]; float s = 0.f, s2 = 0.f;
#pragma unroll
        for (int e = 0; e < 10; e++) {
            vv[e] = swh[t*HR + lane + 32*e];
            s += vv[e]; s2 += vv[e]*vv[e];
        }
#pragma unroll
        for (int o = 16; o > 0; o >>= 1) {
            s  += __shfl_xor_sync(0xffffffffu, s,  o);
            s2 += __shfl_xor_sync(0xffffffffu, s2, o);
        }
        float mu  = s * (1.f/HR);
        float inv = rsqrtf(s2 * (1.f/HR) - mu*mu + LN_EPS);
#pragma unroll
        for (int e = 0; e < 10; e++) {
            int k2 = lane + 32*e;
            g_Wx[(t*B_ + b)*HR + k2] = (vv[e] - mu) * inv * __ldg(&lng[k2]) + __ldg(&lnb[k2]);
        }
    }
}

// ================= main per-batch cluster kernel =================
template<bool UNIF>
__device__ __forceinline__ void run_all(
    float* sm, uint32_t smb, int b, int rank, int tid, int w, int lane,
    const float* __restrict__ h0,  const float* __restrict__ v0,
    const float* __restrict__ dU0, const float* __restrict__ te0,
    const float* __restrict__ tE0,
    const float* __restrict__ h2h_w, const float* __restrict__ h2h_b,
    const float* __restrict__ lnh_g, const float* __restrict__ lnh_b,
    const float* __restrict__ mod2h, const float* __restrict__ tau_v,
    float* __restrict__ outp)
{
    float* o_v   = outp;
    float* o_h   = outp + 16384;
    float* o_dU  = outp + 32768;
    float* o_te  = outp + 4227072;
    float* o_tE  = outp + 4243456;
    float* o_out = outp + 8437760;

    const uint32_t peer = rank ^ 1u;
    const int i0 = rank * 128;
    const int kbase = rank*160 + w*10;
    const bool munif = (g_munif != 0);
    const float m2h0 = g_m2h0;
    const float ra0 = g_ra0, sU0 = g_sU0, sE0 = g_sE0;
    const float bmin = __int_as_float(g_bmin_bits);
    const u64 c_sE2  = pk2(sE0, sE0);
    const u64 c_osE2 = pk2(1.f - sE0, 1.f - sE0);
    const u64 c_osU2 = pk2(1.f - sU0, 1.f - sU0);
    float2* smTE2 = (float2*)sm;   // SM_TE == 0

    // ---------- prologue ----------
    float r_lng = 0.f, r_lnb = 0.f;
    if (tid < HR) { r_lng = lnh_g[tid]; r_lnb = lnh_b[tid]; }

    if (tid < H_) {
        sm[SM_SV + tid]  = sigmoidf(tau_v[tid]);
        sm[SM_H + tid]   = h0[b*H_ + tid];
        sm[SM_TEV + tid] = te0[b*H_ + tid];
        sm[SM_V + tid]   = v0[b*H_ + tid];
    }
    u64 dUr2[8][4];
    {
        const float2* h0p = (const float2*)(h0 + b*H_);
        u64 h0j2[4];
#pragma unroll
        for (int m = 0; m < 4; m++) h0j2[m] = pkf2(h0p[lane + 32*m]);
#pragma unroll
        for (int is = 0; is < 8; is++) {
            int li = w*8 + is;
            int i  = i0 + li;
            const float2* drow = (const float2*)(dU0 + (size_t)(b*H_ + i)*H_);
            const float2* trow = (const float2*)(tE0 + (size_t)(b*H_ + i)*H_);
            u64 acc2 = pk2(0.f, 0.f);
#pragma unroll
            for (int m = 0; m < 4; m++) {
                int p = lane + 32*m;
                float2 d = drow[p];
                smTE2[li*128 + p] = trow[p];
                u64 dv = pkf2(d);
                dUr2[is][m] = dv;
                if (UNIF) acc2 = fma2(dv, h0j2[m], acc2);
                else {
                    const float2* rap = (const float2*)(g_ra + (size_t)i*H_);
                    acc2 = fma2(mul2(pkf2(rap[p]), dv), h0j2[m], acc2);
                }
            }
            float2 af = upk2(acc2);
            float acc = af.x + af.y;
#pragma unroll
            for (int o = 16; o > 0; o >>= 1) acc += __shfl_xor_sync(0xffffffffu, acc, o);
            if (lane == 0) {
                float zi = UNIF ? ra0 * acc : acc;
                sm[SM_Z + i] = zi;
                st_remote(smb + 4u*(SM_Z + i), peer, zi);
            }
        }
    }
    __syncthreads();
    // Wh(0) from h0 (buffer 0)
    {
        const float4* hv4 = (const float4*)&sm[SM_H];
#pragma unroll
        for (int q = 0; q < 10; q++) {
            int k = kbase + q;
            const float4* wr = (const float4*)(h2h_w + (size_t)k*H_);
            float4 wv0 = __ldg(&wr[lane]);
            float4 wv1 = __ldg(&wr[lane + 32]);
            float4 hv0 = hv4[lane];
            float4 hv1 = hv4[lane + 32];
            u64 acc2 = fma2(pk2(wv0.x, wv0.y), pk2(hv0.x, hv0.y), pk2(0.f, 0.f));
            acc2 = fma2(pk2(wv0.z, wv0.w), pk2(hv0.z, hv0.w), acc2);
            acc2 = fma2(pk2(wv1.x, wv1.y), pk2(hv1.x, hv1.y), acc2);
            acc2 = fma2(pk2(wv1.z, wv1.w), pk2(hv1.z, hv1.w), acc2);
            float2 af = upk2(acc2);
            float acc = af.x + af.y;
#pragma unroll
            for (int o = 16; o > 0; o >>= 1) acc += __shfl_xor_sync(0xffffffffu, acc, o);
            if (lane == 0) {
                float vv = acc + __ldg(&h2h_b[k]);
                sm[SM_WH + k] = vv;
                st_remote(smb + 4u*(SM_WH + k), peer, vv);
            }
        }
    }
    CLUSTER_SYNC();

    // ---------- time loop ----------
    for (int t = 0; t < T_; t++) {
        const int hO  = SM_H   + (t & 1)*H_;
        const int hN  = SM_H   + ((t+1) & 1)*H_;
        const int teO = SM_TEV + (t & 1)*H_;
        const int teN = SM_TEV + ((t+1) & 1)*H_;
        const int zR  = SM_Z   + (t & 1)*H_;
        const int zW  = SM_Z   + ((t+1) & 1)*H_;
        const int whR = SM_WH  + (t & 1)*HR;
        const int whW = SM_WH  + ((t+1) & 1)*HR;
        const bool doWh = (t < T_ - 1);

        // ---- small phase (redundant in both CTAs) ----
        float wxv = 0.f;
        if (tid < HR) wxv = __ldg(&g_Wx[(t*B_ + b)*HR + tid]);

        // LN stats: every warp computes redundantly
        float mu, inv;
        {
            float s = 0.f, s2 = 0.f;
#pragma unroll
            for (int e = 0; e < 10; e++) {
                float vv = sm[whR + lane + 32*e];
                s += vv; s2 += vv*vv;
            }
#pragma unroll
            for (int o = 16; o > 0; o >>= 1) {
                s  += __shfl_xor_sync(0xffffffffu, s,  o);
                s2 += __shfl_xor_sync(0xffffffffu, s2, o);
            }
            mu  = s * (1.f/HR);
            inv = rsqrtf(s2 * (1.f/HR) - mu*mu + LN_EPS);
        }
        float whv = 0.f;
        if (tid < HR) {
            whv = (sm[whR + tid] - mu) * inv * r_lng + r_lnb;
            if (tid >= H_) {
                float uval = fmaxf(wxv + whv, 0.f);
                sm[SM_U + tid - H_] = uval;
                if (munif) {   // warps 8,9: fold mod partial sums
#pragma unroll
                    for (int o = 16; o > 0; o >>= 1)
                        uval += __shfl_xor_sync(0xffffffffu, uval, o);
                    if (lane == 0) sm[SM_RED + 40 + (w - 8)] = uval;
                }
            }
        }
        __syncthreads();
        if (tid < H_) {
            float sv = sm[SM_SV + tid];
            float dv = wxv + whv + sm[zR + tid];
            float vo = sm[SM_V + tid];
            float vn = (1.f - sv) * vo + sv * dv;
            sm[SM_V + tid] = vn;
            float nh = fmaxf(vn, 0.f);
            sm[hN + tid] = nh;
            float teo = sm[teO + tid];
            sm[teN + tid] = (1.f - sv) * teo + sv * sm[hO + tid];
            if ((tid >> 7) == rank) o_out[(t*B_ + b)*H_ + tid] = nh;
            float mv;
            if (munif) {
                mv = m2h0 * (sm[SM_RED + 40] + sm[SM_RED + 41]);
            } else {
                mv = 0.f;
                const float4* mr = (const float4*)(mod2h + tid*R_);
#pragma unroll
                for (int r = 0; r < 16; r++) {
                    float4 m4 = __ldg(mr + r);
                    mv += m4.x*sm[SM_U + 4*r] + m4.y*sm[SM_U + 4*r+1]
                        + m4.z*sm[SM_U + 4*r+2] + m4.w*sm[SM_U + 4*r+3];
                }
            }
            sm[SM_MOD + tid] = mv;
        }
        __syncthreads();

        // ---- merged phase: big update (t) + Wh(t+1); partials to smem ----
        {
            const float2* hOp  = (const float2*)&sm[hO];
            const float2* teOp = (const float2*)&sm[teO];
            const float2* hNp  = (const float2*)&sm[hN];
            const float4* hv4  = (const float4*)&sm[hN];
            u64 hnj2[4];
#pragma unroll
            for (int m = 0; m < 4; m++) hnj2[m] = pkf2(hNp[lane + 32*m]);
            // UNIF: hoist sE-scaled j-vectors once per step
            u64 se_te[4], se_ho[4];
            if (UNIF) {
#pragma unroll
                for (int m = 0; m < 4; m++) {
                    int p = lane + 32*m;
                    se_te[m] = mul2(c_sE2, pkf2(teOp[p]));
                    se_ho[m] = mul2(c_sE2, pkf2(hOp[p]));
                }
            }

#pragma unroll
            for (int is = 0; is < 8; is++) {
                float4 wv0, wv1;
                if (doWh) {
                    const float4* wr = (const float4*)(h2h_w + (size_t)(kbase + is)*H_);
                    wv0 = __ldg(&wr[lane]);
                    wv1 = __ldg(&wr[lane + 32]);
                }
                int li = w*8 + is;
                int i  = i0 + li;
                float nh_i  = sm[hN + i];
                float nte_i = sm[teN + i];
                float mod_i = sm[SM_MOD + i];
                u64 nh2   = pk2(nh_i, nh_i);
                u64 mnte2 = pk2(-nte_i, -nte_i);
                u64 acc2  = pk2(0.f, 0.f);
                if (UNIF) {
                    float cm = sU0 * mod_i;
                    u64 cm2 = pk2(cm, cm);
#pragma unroll
                    for (int m = 0; m < 4; m++) {
                        int idx = li*128 + lane + 32*m;
                        u64 tEo = pkf2(smTE2[idx]);
                        u64 tEn = fma2(nh2, se_te[m], mul2(c_osE2, tEo));
                        tEn = fma2(mnte2, se_ho[m], tEn);
                        smTE2[idx] = upk2(tEn);
                        u64 dUn = fma2(c_osU2, dUr2[is][m], mul2(cm2, tEn));
                        float2 dv = upk2(dUn);
                        bool need = fmaxf(fabsf(dv.x), fabsf(dv.y)) > bmin;
                        if (__any_sync(0xffffffffu, need)) {   // rare exact clamp
                            if (need) {
                                int j0 = (i << 8) + 2*(lane + 32*m);
                                float2 hl0 = __ldg(&g_hilo[j0]);
                                float2 hl1 = __ldg(&g_hilo[j0 + 1]);
                                dv.x = fmaxf(fminf(dv.x, hl0.x), hl0.y);
                                dv.y = fmaxf(fminf(dv.y, hl1.x), hl1.y);
                            }
                            dUn = pk2(dv.x, dv.y);
                        }
                        dUr2[is][m] = dUn;
                        acc2 = fma2(dUn, hnj2[m], acc2);
                    }
                } else {
#pragma unroll
                    for (int m = 0; m < 4; m++) {
                        int p = lane + 32*m;
                        int idx = li*128 + p;
                        int j0 = (i << 8) + 2*p;
                        float2 tE2 = smTE2[idx];
                        float2 se2 = *(const float2*)(g_sE + j0);
                        float2 su2 = *(const float2*)(g_sU + j0);
                        float2 ra2 = *(const float2*)(g_ra + j0);
                        float2 ho = hOp[p], te = teOp[p];
                        float2 dUo = upk2(dUr2[is][m]);
                        float ax = nh_i*te.x - nte_i*ho.x;
                        float ay = nh_i*te.y - nte_i*ho.y;
                        float tEnx = (1.f - se2.x)*tE2.x + se2.x*ax;
                        float tEny = (1.f - se2.y)*tE2.y + se2.y*ay;
                        smTE2[idx] = make_float2(tEnx, tEny);
                        float dUx = (1.f - su2.x)*dUo.x + su2.x*mod_i*tEnx;
                        float dUy = (1.f - su2.y)*dUo.y + su2.y*mod_i*tEny;
                        float2 hl0 = __ldg(&g_hilo[j0]);
                        float2 hl1 = __ldg(&g_hilo[j0 + 1]);
                        dUx = fmaxf(fminf(dUx, hl0.x), hl0.y);
                        dUy = fmaxf(fminf(dUy, hl1.x), hl1.y);
                        dUr2[is][m] = pk2(dUx, dUy);
                        acc2 = fma2(pk2(ra2.x*dUx, ra2.y*dUy), hnj2[m], acc2);
                    }
                }
                float2 af = upk2(acc2);
                sm[SM_ZP + li*36 + lane] = af.x + af.y;    // z partial (tree deferred)
                if (doWh) {
                    float4 hv0 = hv4[lane];
                    float4 hv1 = hv4[lane + 32];
                    u64 wa = fma2(pk2(wv0.x, wv0.y), pk2(hv0.x, hv0.y), pk2(0.f, 0.f));
                    wa = fma2(pk2(wv0.z, wv0.w), pk2(hv0.z, hv0.w), wa);
                    wa = fma2(pk2(wv1.x, wv1.y), pk2(hv1.x, hv1.y), wa);
                    wa = fma2(pk2(wv1.z, wv1.w), pk2(hv1.z, hv1.w), wa);
                    float2 wf = upk2(wa);
                    sm[SM_WHP + (w*10 + is)*36 + lane] = wf.x + wf.y;
                }
            }
            if (doWh) {
#pragma unroll
                for (int q = 8; q < 10; q++) {
                    int k = kbase + q;
                    const float4* wr = (const float4*)(h2h_w + (size_t)k*H_);
                    float4 wv0 = __ldg(&wr[lane]);
                    float4 wv1 = __ldg(&wr[lane + 32]);
                    float4 hv0 = hv4[lane];
                    float4 hv1 = hv4[lane + 32];
                    u64 wa = fma2(pk2(wv0.x, wv0.y), pk2(hv0.x, hv0.y), pk2(0.f, 0.f));
                    wa = fma2(pk2(wv0.z, wv0.w), pk2(hv0.z, hv0.w), wa);
                    wa = fma2(pk2(wv1.x, wv1.y), pk2(hv1.x, hv1.y), wa);
                    wa = fma2(pk2(wv1.z, wv1.w), pk2(hv1.z, hv1.w), wa);
                    float2 wf = upk2(wa);
                    sm[SM_WHP + (w*10 + q)*36 + lane] = wf.x + wf.y;
                }
            }
        }
        __syncthreads();

        // ---- reduction pass: all z rows + all Wh rows in parallel ----
        {
            int row = tid >> 2;            // 0..127
            int sub = tid & 3;
            const float4* zp4 = (const float4*)&sm[SM_ZP + row*36 + sub*8];
            float4 a0 = zp4[0], a1 = zp4[1];
            float s = (a0.x + a0.y) + (a0.z + a0.w) + (a1.x + a1.y) + (a1.z + a1.w);
            s += __shfl_xor_sync(0xffffffffu, s, 2);
            s += __shfl_xor_sync(0xffffffffu, s, 1);
            if (sub == 0) {
                int i = i0 + row;
                float zi = UNIF ? ra0 * s : s;
                sm[zW + i] = zi;
                st_remote(smb + 4u*(zW + i), peer, zi);
            }
            if (doWh) {
                int row2 = tid >> 1;       // 0..255
                int sub2 = tid & 1;
                if (row2 < 160) {          // warps 0..9 fully active (warp-uniform)
                    const float4* wp4 = (const float4*)&sm[SM_WHP + row2*36 + sub2*16];
                    float4 b0 = wp4[0], b1 = wp4[1], b2 = wp4[2], b3 = wp4[3];
                    float sw = ((b0.x + b0.y) + (b0.z + b0.w)) + ((b1.x + b1.y) + (b1.z + b1.w))
                             + ((b2.x + b2.y) + (b2.z + b2.w)) + ((b3.x + b3.y) + (b3.z + b3.w));
                    sw += __shfl_xor_sync(0xffffffffu, sw, 1);
                    if (sub2 == 0) {
                        int k = rank*160 + row2;
                        float vv = sw + __ldg(&h2h_b[k]);
                        sm[whW + k] = vv;
                        st_remote(smb + 4u*(whW + k), peer, vv);
                    }
                }
            }
        }
        CLUSTER_SYNC();   // one sync/step: z + Wh(t+1) exchanged
    }

    // ---------- epilogue ----------
#pragma unroll
    for (int is = 0; is < 8; is++) {
        int li = w*8 + is;
        int i  = i0 + li;
        float2* drow = (float2*)(o_dU + (size_t)(b*H_ + i)*H_);
        float2* trow = (float2*)(o_tE + (size_t)(b*H_ + i)*H_);
#pragma unroll
        for (int m = 0; m < 4; m++) {
            int p = lane + 32*m;
            drow[p] = upk2(dUr2[is][m]);
            trow[p] = smTE2[li*128 + p];
        }
    }
    if (tid < 128) {
        int idx = i0 + tid;
        o_v[b*H_ + idx]  = sm[SM_V + idx];
        o_h[b*H_ + idx]  = sm[SM_H + idx];    // T even -> final in buffer 0
        o_te[b*H_ + idx] = sm[SM_TEV + idx];
    }
}

__global__ void __launch_bounds__(NTHR, 1) __cluster_dims__(2, 1, 1)
sgru_cluster(const float* __restrict__ h0,  const float* __restrict__ v0,
             const float* __restrict__ dU0, const float* __restrict__ te0,
             const float* __restrict__ tE0,
             const float* __restrict__ h2h_w, const float* __restrict__ h2h_b,
             const float* __restrict__ lnh_g, const float* __restrict__ lnh_b,
             const float* __restrict__ mod2h, const float* __restrict__ tau_v,
             float* __restrict__ outp)
{
    extern __shared__ float sm[];
    const int tid  = threadIdx.x;
    const int w    = tid >> 5;
    const int lane = tid & 31;
    const int b    = blockIdx.x >> 1;
    const int rank = (int)ctarank();
    const uint32_t smb = s2u(sm);

    if (g_unif) run_all<true >(sm, smb, b, rank, tid, w, lane, h0, v0, dU0, te0, tE0,
                               h2h_w, h2h_b, lnh_g, lnh_b, mod2h, tau_v, outp);
    else        run_all<false>(sm, smb, b, rank, tid, w, lane, h0, v0, dU0, te0, tE0,
                               h2h_w, h2h_b, lnh_g, lnh_b, mod2h, tau_v, outp);
}

extern "C" void kernel_launch(void* const* d_in, const int* in_sizes, int n_in,
                              void* d_out, int out_size) {
    const float* x      = (const float*)d_in[0];
    const float* h0     = (const float*)d_in[1];
    const float* v0     = (const float*)d_in[2];
    const float* dU0    = (const float*)d_in[3];
    const float* te0    = (const float*)d_in[4];
    const float* tE0    = (const float*)d_in[5];
    const float* x2h_w  = (const float*)d_in[6];
    const float* x2h_b  = (const float*)d_in[7];
    const float* h2h_w  = (const float*)d_in[8];
    const float* h2h_b  = (const float*)d_in[9];
    const float* lnx_g  = (const float*)d_in[10];
    const float* lnx_b  = (const float*)d_in[11];
    const float* lnh_g  = (const float*)d_in[12];
    const float* lnh_b  = (const float*)d_in[13];
    const float* alpha  = (const float*)d_in[14];
    const float* mod2h  = (const float*)d_in[15];
    const float* tau_v  = (const float*)d_in[16];
    const float* tau_U  = (const float*)d_in[17];
    const float* tau_E  = (const float*)d_in[18];

    static int smem_set = 0;
    if (!smem_set) {
        cudaFuncSetAttribute(sgru_cluster, cudaFuncAttributeMaxDynamicSharedMemorySize, SM_BYTES);
        smem_set = 1;
    }

    k_aux<<<B_, 640>>>(x, x2h_w, x2h_b, lnx_g, lnx_b,
                       alpha, tau_U, tau_E, h2h_w, mod2h);
    sgru_cluster<<<2*B_, NTHR, SM_BYTES>>>(h0, v0, dU0, te0, tE0,
                                           h2h_w, h2h_b, lnh_g, lnh_b,
                                           mod2h, tau_v, (float*)d_out);
}

// round 12
// speedup vs baseline: 1.6880x; 1.1642x over previous
#include <cuda_runtime.h>
#include <math.h>
#include <stdint.h>

#define T_ 24
#define B_ 64
#define I_ 128
#define H_ 256
#define R_ 64
#define HR 320
#define NTHR 512
#define LN_EPS 1e-5f

// ---- smem float offsets ----
#define SM_TE   0        // 128 rows * 128 float2 = 32768 floats
#define SM_H    32768    // 2*256 ping-pong h
#define SM_TEV  33280    // 2*256 ping-pong te
#define SM_Z    33792    // 2*256 ping-pong z
#define SM_V    34304    // 256
#define SM_MOD  34560    // 256
#define SM_WH   34816    // 2*320 ping-pong Wh
#define SM_SV   35456    // 256
#define SM_U    35712    // 64
#define SM_RED  35776    // 64
#define SM_ZP   35840    // 128 rows * stride 36 = 4608
#define SM_WHP  40448    // 160 rows * stride 36 = 5760
#define SM_TOT  46208
#define SM_BYTES (SM_TOT*4)

// ---- global scratch ----
__device__ float  g_Wx[T_*B_*HR];
__device__ float2 g_hilo[H_*H_];
__device__ float  g_ra[H_*H_];
__device__ float  g_sU[H_*H_];
__device__ float  g_sE[H_*H_];
__device__ int    g_unif = 1;
__device__ int    g_munif = 1;
__device__ int    g_bmin_bits = 0x7f7fffff;
__device__ float  g_ra0, g_sU0, g_sE0, g_m2h0;

typedef unsigned long long u64;

__device__ __forceinline__ float sigmoidf(float x) { return 1.f / (1.f + expf(-x)); }

__device__ __forceinline__ u64 pk2(float lo, float hi) {
    u64 r; asm("mov.b64 %0, {%1, %2};" : "=l"(r) : "f"(lo), "f"(hi)); return r;
}
__device__ __forceinline__ float2 upk2(u64 v) {
    float2 r; asm("mov.b64 {%0, %1}, %2;" : "=f"(r.x), "=f"(r.y) : "l"(v)); return r;
}
__device__ __forceinline__ u64 fma2(u64 a, u64 b, u64 c) {
    u64 r; asm("fma.rn.f32x2 %0, %1, %2, %3;" : "=l"(r) : "l"(a), "l"(b), "l"(c)); return r;
}
__device__ __forceinline__ u64 mul2(u64 a, u64 b) {
    u64 r; asm("mul.rn.f32x2 %0, %1, %2;" : "=l"(r) : "l"(a), "l"(b)); return r;
}
__device__ __forceinline__ u64 pkf2(float2 v) { return pk2(v.x, v.y); }

__device__ __forceinline__ uint32_t s2u(const void* p) {
    uint32_t a;
    asm("{ .reg .u64 t; cvta.to.shared.u64 t, %1; cvt.u32.u64 %0, t; }" : "=r"(a) : "l"(p));
    return a;
}
__device__ __forceinline__ uint32_t ctarank() {
    uint32_t r; asm("mov.u32 %0, %%cluster_ctarank;" : "=r"(r)); return r;
}
__device__ __forceinline__ void st_remote(uint32_t my_addr, uint32_t peer, float v) {
    uint32_t ra;
    asm volatile("mapa.shared::cluster.u32 %0, %1, %2;" : "=r"(ra) : "r"(my_addr), "r"(peer));
    asm volatile("st.shared::cluster.f32 [%0], %1;" :: "r"(ra), "f"(v) : "memory");
}
#define CLUSTER_SYNC() do { \
    asm volatile("barrier.cluster.arrive.aligned;" ::: "memory"); \
    asm volatile("barrier.cluster.wait.aligned;" ::: "memory"); } while (0)

// -------- per-element prep (warp-reduced atomics; flags statically initialized;
// atomics only tighten -> converged & deterministic across graph replays) --------
__device__ __forceinline__ void prep_elem(int idx, int lane,
                                          const float* __restrict__ alpha,
                                          const float* __restrict__ tauU,
                                          const float* __restrict__ tauE,
                                          const float* __restrict__ h2h_w,
                                          const float* __restrict__ mod2h) {
    float a = alpha[idx], u = tauU[idx], e = tauE[idx];
    float ra = fmaxf(a, 0.f);
    g_ra[idx] = ra;
    g_sU[idx] = sigmoidf(u);
    g_sE[idx] = sigmoidf(e);
    float wv = h2h_w[idx];
    float den = ra + 1e-8f;
    float hi = fmaxf(1.f - wv, 0.f) / den;
    float lo = -fmaxf(1.f + wv, 0.f) / den;
    g_hilo[idx] = make_float2(hi, lo);
    float bnd = fminf(hi, -lo);            // >= 0
#pragma unroll
    for (int o = 16; o > 0; o >>= 1) bnd = fminf(bnd, __shfl_xor_sync(0xffffffffu, bnd, o));
    bool eq = (a == alpha[0]) && (u == tauU[0]) && (e == tauE[0]);
    bool alleq = __all_sync(0xffffffffu, eq);
    if (lane == 0) {
        atomicMin(&g_bmin_bits, __float_as_int(bnd));  // bnd >= 0: int order == float order
        if (!alleq) atomicAnd(&g_unif, 0);
    }
    if (idx < H_ * R_) {                    // warp-uniform (512-aligned blocks)
        bool meq = (mod2h[idx] == mod2h[0]);
        bool allm = __all_sync(0xffffffffu, meq);
        if (lane == 0 && !allm) atomicAnd(&g_munif, 0);
    }
    if (idx == 0) {
        g_ra0 = ra; g_sU0 = sigmoidf(u); g_sE0 = sigmoidf(e); g_m2h0 = mod2h[0];
    }
}

// -------- fused aux: prep (512 elems/block) + weight-stationary Wx over t-half --------
#define TH_ 12
__global__ void __launch_bounds__(640, 1)
k_aux(const float* __restrict__ x,
      const float* __restrict__ w,
      const float* __restrict__ bias,
      const float* __restrict__ lng,
      const float* __restrict__ lnb,
      const float* __restrict__ alpha,
      const float* __restrict__ tauU,
      const float* __restrict__ tauE,
      const float* __restrict__ h2h_w,
      const float* __restrict__ mod2h) {
    int bid = blockIdx.x;                // 0..127
    int b   = bid >> 1;
    int t0  = (bid & 1) * TH_;           // t-half offset
    int tid = threadIdx.x;               // 0..639
    int lane = tid & 31;
    __shared__ float sx[TH_*I_];         // 1536
    __shared__ float swh[TH_*HR];        // 3840

    // ---- prep portion: 512 elems/block (warps 0..15 only; full masks) ----
    if (tid < 512) prep_elem(bid*512 + tid, lane, alpha, tauU, tauE, h2h_w, mod2h);

    // ---- Wx portion (t in [t0, t0+12)) ----
    for (int idx = tid; idx < TH_*I_; idx += 640)
        sx[idx] = x[((idx >> 7) + t0)*(B_*I_) + b*I_ + (idx & 127)];

    int k = tid >> 1;                    // row 0..319
    int half = tid & 1;
    const float4* wr = (const float4*)(w + (size_t)k*I_ + half*64);
    float4 wreg[16];
#pragma unroll
    for (int m = 0; m < 16; m++) wreg[m] = __ldg(&wr[m]);
    float bk = bias[k];
    __syncthreads();

#pragma unroll
    for (int q = 0; q < TH_; q++) {
        const float4* xb4 = (const float4*)&sx[q*I_ + half*64];
        float acc = 0.f;
#pragma unroll
        for (int m = 0; m < 16; m++) {
            float4 wv = wreg[m];
            float4 xv = xb4[m];
            acc += wv.x*xv.x + wv.y*xv.y + wv.z*xv.z + wv.w*xv.w;
        }
        acc += __shfl_xor_sync(0xffffffffu, acc, 1);
        if (half == 0) swh[q*HR + k] = acc + bk;
    }
    __syncthreads();

    int wid = tid >> 5;
    if (wid < TH_) {                     // warps 0..11, one t each
        int q = wid;
        float vv[10]; float s = 0.f, s2 = 0.f;
#pragma unroll
        for (int e = 0; e < 10; e++) {
            vv[e] = swh[q*HR + lane + 32*e];
            s += vv[e]; s2 += vv[e]*vv[e];
        }
#pragma unroll
        for (int o = 16; o > 0; o >>= 1) {
            s  += __shfl_xor_sync(0xffffffffu, s,  o);
            s2 += __shfl_xor_sync(0xffffffffu, s2, o);
        }
        float mu  = s * (1.f/HR);
        float inv = rsqrtf(s2 * (1.f/HR) - mu*mu + LN_EPS);
#pragma unroll
        for (int e = 0; e < 10; e++) {
            int k2 = lane + 32*e;
            g_Wx[((q + t0)*B_ + b)*HR + k2] = (vv[e] - mu) * inv * __ldg(&lng[k2]) + __ldg(&lnb[k2]);
        }
    }
}

// ================= main per-batch cluster kernel =================
template<bool UNIF>
__device__ __forceinline__ void run_all(
    float* sm, uint32_t smb, int b, int rank, int tid, int w, int lane,
    const float* __restrict__ h0,  const float* __restrict__ v0,
    const float* __restrict__ dU0, const float* __restrict__ te0,
    const float* __restrict__ tE0,
    const float* __restrict__ h2h_w, const float* __restrict__ h2h_b,
    const float* __restrict__ lnh_g, const float* __restrict__ lnh_b,
    const float* __restrict__ mod2h, const float* __restrict__ tau_v,
    float* __restrict__ outp)
{
    float* o_v   = outp;
    float* o_h   = outp + 16384;
    float* o_dU  = outp + 32768;
    float* o_te  = outp + 4227072;
    float* o_tE  = outp + 4243456;
    float* o_out = outp + 8437760;

    const uint32_t peer = rank ^ 1u;
    const int i0 = rank * 128;
    const int kbase = rank*160 + w*10;
    const bool munif = (g_munif != 0);
    const float m2h0 = g_m2h0;
    const float ra0 = g_ra0, sU0 = g_sU0, sE0 = g_sE0;
    const float bmin = __int_as_float(g_bmin_bits);
    const u64 c_sE2  = pk2(sE0, sE0);
    const u64 c_osE2 = pk2(1.f - sE0, 1.f - sE0);
    const u64 c_osU2 = pk2(1.f - sU0, 1.f - sU0);
    float2* smTE2 = (float2*)sm;   // SM_TE == 0

    // ---------- prologue ----------
    float r_lng = 0.f, r_lnb = 0.f;
    if (tid < HR) { r_lng = lnh_g[tid]; r_lnb = lnh_b[tid]; }

    if (tid < H_) {
        sm[SM_SV + tid]  = sigmoidf(tau_v[tid]);
        sm[SM_H + tid]   = h0[b*H_ + tid];
        sm[SM_TEV + tid] = te0[b*H_ + tid];
        sm[SM_V + tid]   = v0[b*H_ + tid];
    }
    u64 dUr2[8][4];
    {
        const float2* h0p = (const float2*)(h0 + b*H_);
        u64 h0j2[4];
#pragma unroll
        for (int m = 0; m < 4; m++) h0j2[m] = pkf2(h0p[lane + 32*m]);
#pragma unroll
        for (int is = 0; is < 8; is++) {
            int li = w*8 + is;
            int i  = i0 + li;
            const float2* drow = (const float2*)(dU0 + (size_t)(b*H_ + i)*H_);
            const float2* trow = (const float2*)(tE0 + (size_t)(b*H_ + i)*H_);
            u64 acc2 = pk2(0.f, 0.f);
#pragma unroll
            for (int m = 0; m < 4; m++) {
                int p = lane + 32*m;
                float2 d = drow[p];
                smTE2[li*128 + p] = trow[p];
                u64 dv = pkf2(d);
                dUr2[is][m] = dv;
                if (UNIF) acc2 = fma2(dv, h0j2[m], acc2);
                else {
                    const float2* rap = (const float2*)(g_ra + (size_t)i*H_);
                    acc2 = fma2(mul2(pkf2(rap[p]), dv), h0j2[m], acc2);
                }
            }
            float2 af = upk2(acc2);
            float acc = af.x + af.y;
#pragma unroll
            for (int o = 16; o > 0; o >>= 1) acc += __shfl_xor_sync(0xffffffffu, acc, o);
            if (lane == 0) {
                float zi = UNIF ? ra0 * acc : acc;
                sm[SM_Z + i] = zi;
                st_remote(smb + 4u*(SM_Z + i), peer, zi);
            }
        }
    }
    __syncthreads();
    // Wh(0) from h0 (buffer 0)
    {
        const float4* hv4 = (const float4*)&sm[SM_H];
#pragma unroll
        for (int q = 0; q < 10; q++) {
            int k = kbase + q;
            const float4* wr = (const float4*)(h2h_w + (size_t)k*H_);
            float4 wv0 = __ldg(&wr[lane]);
            float4 wv1 = __ldg(&wr[lane + 32]);
            float4 hv0 = hv4[lane];
            float4 hv1 = hv4[lane + 32];
            u64 acc2 = fma2(pk2(wv0.x, wv0.y), pk2(hv0.x, hv0.y), pk2(0.f, 0.f));
            acc2 = fma2(pk2(wv0.z, wv0.w), pk2(hv0.z, hv0.w), acc2);
            acc2 = fma2(pk2(wv1.x, wv1.y), pk2(hv1.x, hv1.y), acc2);
            acc2 = fma2(pk2(wv1.z, wv1.w), pk2(hv1.z, hv1.w), acc2);
            float2 af = upk2(acc2);
            float acc = af.x + af.y;
#pragma unroll
            for (int o = 16; o > 0; o >>= 1) acc += __shfl_xor_sync(0xffffffffu, acc, o);
            if (lane == 0) {
                float vv = acc + __ldg(&h2h_b[k]);
                sm[SM_WH + k] = vv;
                st_remote(smb + 4u*(SM_WH + k), peer, vv);
            }
        }
    }
    CLUSTER_SYNC();

    // ---------- time loop ----------
    for (int t = 0; t < T_; t++) {
        const int hO  = SM_H   + (t & 1)*H_;
        const int hN  = SM_H   + ((t+1) & 1)*H_;
        const int teO = SM_TEV + (t & 1)*H_;
        const int teN = SM_TEV + ((t+1) & 1)*H_;
        const int zR  = SM_Z   + (t & 1)*H_;
        const int zW  = SM_Z   + ((t+1) & 1)*H_;
        const int whR = SM_WH  + (t & 1)*HR;
        const int whW = SM_WH  + ((t+1) & 1)*HR;
        const bool doWh = (t < T_ - 1);

        // ---- small phase (redundant in both CTAs) ----
        float wxv = 0.f;
        if (tid < HR) wxv = __ldg(&g_Wx[(t*B_ + b)*HR + tid]);

        // LN stats: every warp computes redundantly
        float mu, inv;
        {
            float s = 0.f, s2 = 0.f;
#pragma unroll
            for (int e = 0; e < 10; e++) {
                float vv = sm[whR + lane + 32*e];
                s += vv; s2 += vv*vv;
            }
#pragma unroll
            for (int o = 16; o > 0; o >>= 1) {
                s  += __shfl_xor_sync(0xffffffffu, s,  o);
                s2 += __shfl_xor_sync(0xffffffffu, s2, o);
            }
            mu  = s * (1.f/HR);
            inv = rsqrtf(s2 * (1.f/HR) - mu*mu + LN_EPS);
        }
        float whv = 0.f;
        if (tid < HR) {
            whv = (sm[whR + tid] - mu) * inv * r_lng + r_lnb;
            if (tid >= H_) {
                float uval = fmaxf(wxv + whv, 0.f);
                sm[SM_U + tid - H_] = uval;
                if (munif) {   // warps 8,9: fold mod partial sums
#pragma unroll
                    for (int o = 16; o > 0; o >>= 1)
                        uval += __shfl_xor_sync(0xffffffffu, uval, o);
                    if (lane == 0) sm[SM_RED + 40 + (w - 8)] = uval;
                }
            }
        }
        __syncthreads();
        if (tid < H_) {
            float sv = sm[SM_SV + tid];
            float dv = wxv + whv + sm[zR + tid];
            float vo = sm[SM_V + tid];
            float vn = (1.f - sv) * vo + sv * dv;
            sm[SM_V + tid] = vn;
            float nh = fmaxf(vn, 0.f);
            sm[hN + tid] = nh;
            float teo = sm[teO + tid];
            sm[teN + tid] = (1.f - sv) * teo + sv * sm[hO + tid];
            if ((tid >> 7) == rank) o_out[(t*B_ + b)*H_ + tid] = nh;
            float mv;
            if (munif) {
                mv = m2h0 * (sm[SM_RED + 40] + sm[SM_RED + 41]);
            } else {
                mv = 0.f;
                const float4* mr = (const float4*)(mod2h + tid*R_);
#pragma unroll
                for (int r = 0; r < 16; r++) {
                    float4 m4 = __ldg(mr + r);
                    mv += m4.x*sm[SM_U + 4*r] + m4.y*sm[SM_U + 4*r+1]
                        + m4.z*sm[SM_U + 4*r+2] + m4.w*sm[SM_U + 4*r+3];
                }
            }
            sm[SM_MOD + tid] = mv;
        }
        __syncthreads();

        // ---- merged phase: big update (t) + Wh(t+1); partials to smem ----
        {
            const float2* hOp  = (const float2*)&sm[hO];
            const float2* teOp = (const float2*)&sm[teO];
            const float2* hNp  = (const float2*)&sm[hN];
            const float4* hv4  = (const float4*)&sm[hN];
            u64 hnj2[4];
#pragma unroll
            for (int m = 0; m < 4; m++) hnj2[m] = pkf2(hNp[lane + 32*m]);
            // UNIF: hoist sE-scaled j-vectors once per step
            u64 se_te[4], se_ho[4];
            if (UNIF) {
#pragma unroll
                for (int m = 0; m < 4; m++) {
                    int p = lane + 32*m;
                    se_te[m] = mul2(c_sE2, pkf2(teOp[p]));
                    se_ho[m] = mul2(c_sE2, pkf2(hOp[p]));
                }
            }

#pragma unroll
            for (int is = 0; is < 8; is++) {
                float4 wv0, wv1;
                if (doWh) {
                    const float4* wr = (const float4*)(h2h_w + (size_t)(kbase + is)*H_);
                    wv0 = __ldg(&wr[lane]);
                    wv1 = __ldg(&wr[lane + 32]);
                }
                int li = w*8 + is;
                int i  = i0 + li;
                float nh_i  = sm[hN + i];
                float nte_i = sm[teN + i];
                float mod_i = sm[SM_MOD + i];
                u64 nh2   = pk2(nh_i, nh_i);
                u64 mnte2 = pk2(-nte_i, -nte_i);
                u64 acc2  = pk2(0.f, 0.f);
                if (UNIF) {
                    float cm = sU0 * mod_i;
                    u64 cm2 = pk2(cm, cm);
                    float needmax = 0.f;
#pragma unroll
                    for (int m = 0; m < 4; m++) {
                        int idx = li*128 + lane + 32*m;
                        u64 tEo = pkf2(smTE2[idx]);
                        u64 tEn = fma2(nh2, se_te[m], mul2(c_osE2, tEo));
                        tEn = fma2(mnte2, se_ho[m], tEn);
                        smTE2[idx] = upk2(tEn);
                        u64 dUn = fma2(c_osU2, dUr2[is][m], mul2(cm2, tEn));
                        dUr2[is][m] = dUn;
                        float2 dv = upk2(dUn);
                        needmax = fmaxf(needmax, fmaxf(fabsf(dv.x), fabsf(dv.y)));
                    }
                    // one vote per row (rare exact clamp path)
                    if (__any_sync(0xffffffffu, needmax > bmin)) {
#pragma unroll
                        for (int m = 0; m < 4; m++) {
                            float2 dv = upk2(dUr2[is][m]);
                            if (fmaxf(fabsf(dv.x), fabsf(dv.y)) > bmin) {
                                int j0 = (i << 8) + 2*(lane + 32*m);
                                float2 hl0 = __ldg(&g_hilo[j0]);
                                float2 hl1 = __ldg(&g_hilo[j0 + 1]);
                                dv.x = fmaxf(fminf(dv.x, hl0.x), hl0.y);
                                dv.y = fmaxf(fminf(dv.y, hl1.x), hl1.y);
                                dUr2[is][m] = pk2(dv.x, dv.y);
                            }
                        }
                    }
#pragma unroll
                    for (int m = 0; m < 4; m++) acc2 = fma2(dUr2[is][m], hnj2[m], acc2);
                } else {
#pragma unroll
                    for (int m = 0; m < 4; m++) {
                        int p = lane + 32*m;
                        int idx = li*128 + p;
                        int j0 = (i << 8) + 2*p;
                        float2 tE2 = smTE2[idx];
                        float2 se2 = *(const float2*)(g_sE + j0);
                        float2 su2 = *(const float2*)(g_sU + j0);
                        float2 ra2 = *(const float2*)(g_ra + j0);
                        float2 ho = hOp[p], te = teOp[p];
                        float2 dUo = upk2(dUr2[is][m]);
                        float ax = nh_i*te.x - nte_i*ho.x;
                        float ay = nh_i*te.y - nte_i*ho.y;
                        float tEnx = (1.f - se2.x)*tE2.x + se2.x*ax;
                        float tEny = (1.f - se2.y)*tE2.y + se2.y*ay;
                        smTE2[idx] = make_float2(tEnx, tEny);
                        float dUx = (1.f - su2.x)*dUo.x + su2.x*mod_i*tEnx;
                        float dUy = (1.f - su2.y)*dUo.y + su2.y*mod_i*tEny;
                        float2 hl0 = __ldg(&g_hilo[j0]);
                        float2 hl1 = __ldg(&g_hilo[j0 + 1]);
                        dUx = fmaxf(fminf(dUx, hl0.x), hl0.y);
                        dUy = fmaxf(fminf(dUy, hl1.x), hl1.y);
                        dUr2[is][m] = pk2(dUx, dUy);
                        acc2 = fma2(pk2(ra2.x*dUx, ra2.y*dUy), hnj2[m], acc2);
                    }
                }
                float2 af = upk2(acc2);
                sm[SM_ZP + li*36 + lane] = af.x + af.y;    // z partial (tree deferred)
                if (doWh) {
                    float4 hv0 = hv4[lane];
                    float4 hv1 = hv4[lane + 32];
                    u64 wa = fma2(pk2(wv0.x, wv0.y), pk2(hv0.x, hv0.y), pk2(0.f, 0.f));
                    wa = fma2(pk2(wv0.z, wv0.w), pk2(hv0.z, hv0.w), wa);
                    wa = fma2(pk2(wv1.x, wv1.y), pk2(hv1.x, hv1.y), wa);
                    wa = fma2(pk2(wv1.z, wv1.w), pk2(hv1.z, hv1.w), wa);
                    float2 wf = upk2(wa);
                    sm[SM_WHP + (w*10 + is)*36 + lane] = wf.x + wf.y;
                }
            }
            if (doWh) {
#pragma unroll
                for (int q = 8; q < 10; q++) {
                    int k = kbase + q;
                    const float4* wr = (const float4*)(h2h_w + (size_t)k*H_);
                    float4 wv0 = __ldg(&wr[lane]);
                    float4 wv1 = __ldg(&wr[lane + 32]);
                    float4 hv0 = hv4[lane];
                    float4 hv1 = hv4[lane + 32];
                    u64 wa = fma2(pk2(wv0.x, wv0.y), pk2(hv0.x, hv0.y), pk2(0.f, 0.f));
                    wa = fma2(pk2(wv0.z, wv0.w), pk2(hv0.z, hv0.w), wa);
                    wa = fma2(pk2(wv1.x, wv1.y), pk2(hv1.x, hv1.y), wa);
                    wa = fma2(pk2(wv1.z, wv1.w), pk2(hv1.z, hv1.w), wa);
                    float2 wf = upk2(wa);
                    sm[SM_WHP + (w*10 + q)*36 + lane] = wf.x + wf.y;
                }
            }
        }
        __syncthreads();

        // ---- reduction pass: all z rows + all Wh rows in parallel ----
        {
            int row = tid >> 2;            // 0..127
            int sub = tid & 3;
            const float4* zp4 = (const float4*)&sm[SM_ZP + row*36 + sub*8];
            float4 a0 = zp4[0], a1 = zp4[1];
            float s = (a0.x + a0.y) + (a0.z + a0.w) + (a1.x + a1.y) + (a1.z + a1.w);
            s += __shfl_xor_sync(0xffffffffu, s, 2);
            s += __shfl_xor_sync(0xffffffffu, s, 1);
            if (sub == 0) {
                int i = i0 + row;
                float zi = UNIF ? ra0 * s : s;
                sm[zW + i] = zi;
                st_remote(smb + 4u*(zW + i), peer, zi);
            }
            if (doWh) {
                int row2 = tid >> 1;       // 0..255
                int sub2 = tid & 1;
                if (row2 < 160) {          // warps 0..9 fully active (warp-uniform)
                    const float4* wp4 = (const float4*)&sm[SM_WHP + row2*36 + sub2*16];
                    float4 b0 = wp4[0], b1 = wp4[1], b2 = wp4[2], b3 = wp4[3];
                    float sw = ((b0.x + b0.y) + (b0.z + b0.w)) + ((b1.x + b1.y) + (b1.z + b1.w))
                             + ((b2.x + b2.y) + (b2.z + b2.w)) + ((b3.x + b3.y) + (b3.z + b3.w));
                    sw += __shfl_xor_sync(0xffffffffu, sw, 1);
                    if (sub2 == 0) {
                        int k = rank*160 + row2;
                        float vv = sw + __ldg(&h2h_b[k]);
                        sm[whW + k] = vv;
                        st_remote(smb + 4u*(whW + k), peer, vv);
                    }
                }
            }
        }
        CLUSTER_SYNC();   // one sync/step: z + Wh(t+1) exchanged
    }

    // ---------- epilogue ----------
#pragma unroll
    for (int is = 0; is < 8; is++) {
        int li = w*8 + is;
        int i  = i0 + li;
        float2* drow = (float2*)(o_dU + (size_t)(b*H_ + i)*H_);
        float2* trow = (float2*)(o_tE + (size_t)(b*H_ + i)*H_);
#pragma unroll
        for (int m = 0; m < 4; m++) {
            int p = lane + 32*m;
            drow[p] = upk2(dUr2[is][m]);
            trow[p] = smTE2[li*128 + p];
        }
    }
    if (tid < 128) {
        int idx = i0 + tid;
        o_v[b*H_ + idx]  = sm[SM_V + idx];
        o_h[b*H_ + idx]  = sm[SM_H + idx];    // T even -> final in buffer 0
        o_te[b*H_ + idx] = sm[SM_TEV + idx];
    }
}

__global__ void __launch_bounds__(NTHR, 1) __cluster_dims__(2, 1, 1)
sgru_cluster(const float* __restrict__ h0,  const float* __restrict__ v0,
             const float* __restrict__ dU0, const float* __restrict__ te0,
             const float* __restrict__ tE0,
             const float* __restrict__ h2h_w, const float* __restrict__ h2h_b,
             const float* __restrict__ lnh_g, const float* __restrict__ lnh_b,
             const float* __restrict__ mod2h, const float* __restrict__ tau_v,
             float* __restrict__ outp)
{
    extern __shared__ float sm[];
    const int tid  = threadIdx.x;
    const int w    = tid >> 5;
    const int lane = tid & 31;
    const int b    = blockIdx.x >> 1;
    const int rank = (int)ctarank();
    const uint32_t smb = s2u(sm);

    if (g_unif) run_all<true >(sm, smb, b, rank, tid, w, lane, h0, v0, dU0, te0, tE0,
                               h2h_w, h2h_b, lnh_g, lnh_b, mod2h, tau_v, outp);
    else        run_all<false>(sm, smb, b, rank, tid, w, lane, h0, v0, dU0, te0, tE0,
                               h2h_w, h2h_b, lnh_g, lnh_b, mod2h, tau_v, outp);
}

extern "C" void kernel_launch(void* const* d_in, const int* in_sizes, int n_in,
                              void* d_out, int out_size) {
    const float* x      = (const float*)d_in[0];
    const float* h0     = (const float*)d_in[1];
    const float* v0     = (const float*)d_in[2];
    const float* dU0    = (const float*)d_in[3];
    const float* te0    = (const float*)d_in[4];
    const float* tE0    = (const float*)d_in[5];
    const float* x2h_w  = (const float*)d_in[6];
    const float* x2h_b  = (const float*)d_in[7];
    const float* h2h_w  = (const float*)d_in[8];
    const float* h2h_b  = (const float*)d_in[9];
    const float* lnx_g  = (const float*)d_in[10];
    const float* lnx_b  = (const float*)d_in[11];
    const float* lnh_g  = (const float*)d_in[12];
    const float* lnh_b  = (const float*)d_in[13];
    const float* alpha  = (const float*)d_in[14];
    const float* mod2h  = (const float*)d_in[15];
    const float* tau_v  = (const float*)d_in[16];
    const float* tau_U  = (const float*)d_in[17];
    const float* tau_E  = (const float*)d_in[18];

    static int smem_set = 0;
    if (!smem_set) {
        cudaFuncSetAttribute(sgru_cluster, cudaFuncAttributeMaxDynamicSharedMemorySize, SM_BYTES);
        smem_set = 1;
    }

    k_aux<<<2*B_, 640>>>(x, x2h_w, x2h_b, lnx_g, lnx_b,
                         alpha, tau_U, tau_E, h2h_w, mod2h);
    sgru_cluster<<<2*B_, NTHR, SM_BYTES>>>(h0, v0, dU0, te0, tE0,
                                           h2h_w, h2h_b, lnh_g, lnh_b,
                                           mod2h, tau_v, (float*)d_out);
}